// round 7
// baseline (speedup 1.0000x reference)
#include <cuda_runtime.h>
#include <cuda_bf16.h>
#include <cstdint>
#include <math.h>

#define NB 16
#define NH 16
#define NTOK 740
#define HD 32
#define CDIM 512
#define MROWS (NB * NTOK)            // 11840
#define BHND (NB * NH * NTOK * HD)   // 6062080
#define QK_SCALE 0.17677669529663687f

// ---------------- device scratch ----------------
__device__ __align__(16) float g_bias[NH * NTOK * NTOK + 256];
__device__ __align__(16) __nv_bfloat16 g_Ahi[MROWS * CDIM];   // attn out split
__device__ __align__(16) __nv_bfloat16 g_Alo[MROWS * CDIM];
__device__ __align__(16) __nv_bfloat16 g_Whi[3 * CDIM * CDIM]; // W_qkv^T [1536,512]
__device__ __align__(16) __nv_bfloat16 g_Wlo[3 * CDIM * CDIM];
__device__ __align__(16) __nv_bfloat16 g_Phi[CDIM * CDIM];     // W_proj^T [512,512]
__device__ __align__(16) __nv_bfloat16 g_Plo[CDIM * CDIM];
__device__ __align__(16) __nv_bfloat16 g_q_hi[BHND];
__device__ __align__(16) __nv_bfloat16 g_q_lo[BHND];
__device__ __align__(16) __nv_bfloat16 g_k_hi[BHND];
__device__ __align__(16) __nv_bfloat16 g_k_lo[BHND];
__device__ __align__(16) __nv_bfloat16 g_v_hi[BHND];
__device__ __align__(16) __nv_bfloat16 g_v_lo[BHND];

// ================= helpers (base ISA only) =================
__device__ __forceinline__ uint32_t smem_u32(const void* p) {
    uint32_t a;
    asm("{ .reg .u64 t; cvta.to.shared.u64 t, %1; cvt.u32.u64 %0, t; }" : "=r"(a) : "l"(p));
    return a;
}

__device__ __forceinline__ void mma16816(float c[4], const uint32_t a[4],
                                         uint32_t b0, uint32_t b1) {
    asm volatile(
        "mma.sync.aligned.m16n8k16.row.col.f32.bf16.bf16.f32 "
        "{%0,%1,%2,%3}, {%4,%5,%6,%7}, {%8,%9}, {%0,%1,%2,%3};"
        : "+f"(c[0]), "+f"(c[1]), "+f"(c[2]), "+f"(c[3])
        : "r"(a[0]), "r"(a[1]), "r"(a[2]), "r"(a[3]), "r"(b0), "r"(b1));
}

#define LDSM4(R0, R1, R2, R3, ADDR) \
    asm volatile("ldmatrix.sync.aligned.m8n8.x4.shared.b16 {%0,%1,%2,%3}, [%4];" \
        : "=r"(R0), "=r"(R1), "=r"(R2), "=r"(R3) : "r"(ADDR))

#define LDSM4T(R0, R1, R2, R3, ADDR) \
    asm volatile("ldmatrix.sync.aligned.m8n8.x4.trans.shared.b16 {%0,%1,%2,%3}, [%4];" \
        : "=r"(R0), "=r"(R1), "=r"(R2), "=r"(R3) : "r"(ADDR))

#define CP16(dst, src) \
    asm volatile("cp.async.cg.shared.global [%0], [%1], 16;" :: "r"(dst), "l"(src))
#define CPCOMMIT() asm volatile("cp.async.commit_group;" ::: "memory")
#define CPWAIT1() asm volatile("cp.async.wait_group 1;" ::: "memory")

__device__ __forceinline__ void split_pack2(float f0, float f1,
                                            uint32_t& hi, uint32_t& lo) {
    __nv_bfloat16 h0 = __float2bfloat16(f0);
    __nv_bfloat16 h1 = __float2bfloat16(f1);
    __nv_bfloat162 hv(h0, h1);
    hi = *reinterpret_cast<uint32_t*>(&hv);
    __nv_bfloat162 lv(__float2bfloat16(f0 - __bfloat162float(h0)),
                      __float2bfloat16(f1 - __bfloat162float(h1)));
    lo = *reinterpret_cast<uint32_t*>(&lv);
}

__device__ __forceinline__ int imin(int a, int b) { return a < b ? a : b; }

// =====================================================================
// Bias assembly
// =====================================================================
__global__ void build_bias_kernel(const float* __restrict__ btt,
                                  const float* __restrict__ btm,
                                  const float* __restrict__ ttt,
                                  const float* __restrict__ tgt,
                                  const float* __restrict__ ttl,
                                  const float* __restrict__ tgl)
{
    int p = blockIdx.x * 256 + threadIdx.x;
    if (p >= NTOK * NTOK) return;
    int h = blockIdx.y;
    int i = p / NTOK, j = p - i * NTOK;
    float v;
    if (i < 256) {
        if (j < 256) {
            int ai = i >> 4, bi = i & 15, aj = j >> 4, bj = j & 15;
            int idx = (ai - aj + 15) * 31 + (bi - bj + 15);
            v = btm[idx * NH + h];
        } else {
            v = tgt[h * 256 + i] + tgl[h * 484 + (j - 256)];
        }
    } else {
        int i2 = i - 256;
        if (j < 256) {
            v = ttt[h * 484 + i2] + ttl[h * 256 + j];
        } else {
            int j2 = j - 256;
            int ai = i2 / 22, bi = i2 - ai * 22;
            int aj = j2 / 22, bj = j2 - aj * 22;
            int idx = (ai - aj + 21) * 43 + (bi - bj + 21);
            v = btt[idx * NH + h];
        }
    }
    g_bias[h * NTOK * NTOK + p] = v;
}

// =====================================================================
// Transpose + split: W[K,NN] fp32 -> hi/lo[NN,K] bf16
// =====================================================================
__global__ void tsplit_kernel(const float* __restrict__ W,
                              __nv_bfloat16* __restrict__ hi,
                              __nv_bfloat16* __restrict__ lo, int K, int NN)
{
    __shared__ float t[32][33];
    int nb = blockIdx.x * 32, kb = blockIdx.y * 32;
    int tx = threadIdx.x, ty = threadIdx.y;
#pragma unroll
    for (int i = 0; i < 32; i += 8)
        t[ty + i][tx] = W[(size_t)(kb + ty + i) * NN + nb + tx];
    __syncthreads();
#pragma unroll
    for (int i = 0; i < 32; i += 8) {
        float v = t[tx][ty + i];
        __nv_bfloat16 h = __float2bfloat16(v);
        __nv_bfloat16 l = __float2bfloat16(v - __bfloat162float(h));
        size_t o = (size_t)(nb + ty + i) * K + kb + tx;
        hi[o] = h;
        lo[o] = l;
    }
}

// =====================================================================
// HMMA split-bf16 GEMM, cp.async double-buffered.
// MODE 0: A = fp32 x, split inline; epilogue -> q/k/v split bf16, q scaled
// MODE 1: A = pre-split (g_Ahi/g_Alo); epilogue -> fp32 out
// smem per stage (bytes): Ahi 0 | Alo 10240 | Bhi 20480 | Blo 30720 ; stride 40960
// =====================================================================
#define G_STAGE 40960
#define G_SMEM (2 * G_STAGE)

template <int MODE>
__global__ void __launch_bounds__(256) gemm_mma_kernel(
    const float* __restrict__ A32,
    const __nv_bfloat16* __restrict__ Ahi, const __nv_bfloat16* __restrict__ Alo,
    const __nv_bfloat16* __restrict__ Bhi, const __nv_bfloat16* __restrict__ Blo,
    const float* __restrict__ bias, float* __restrict__ out)
{
    extern __shared__ __align__(16) char smraw[];
    uint32_t sb = smem_u32(smraw);
    int tid = threadIdx.x, lane = tid & 31, wid = tid >> 5;
    int wm = wid >> 1, wn = wid & 1;
    int m0 = blockIdx.y * 128, n0 = blockIdx.x * 128;
    int qr = lane >> 2, qc2 = (lane & 3) * 2;

    float acc[16][4];
#pragma unroll
    for (int i = 0; i < 16; i++)
#pragma unroll
        for (int j = 0; j < 4; j++) acc[i][j] = 0.f;

    int r = tid >> 1;
    int e0 = (tid & 1) * 16;                 // element offset within 32-col tile row
    uint32_t rowoff = (uint32_t)(r * 40 + e0) * 2;  // byte offset in a 128x40-bf16 matrix
    int arow = imin(m0 + r, MROWS - 1);
    int brow = n0 + r;

    const char* pBhi = (const char*)(Bhi + (size_t)brow * CDIM + e0);
    const char* pBlo = (const char*)(Blo + (size_t)brow * CDIM + e0);
    const char* pAhi = (const char*)(Ahi + (size_t)arow * CDIM + e0);
    const char* pAlo = (const char*)(Alo + (size_t)arow * CDIM + e0);
    const float* pA32 = A32 + (size_t)arow * CDIM + e0;

    float a32[16];

    // ---- prologue: tile 0 ----
    {
        uint32_t s0 = sb;
        CP16(s0 + 20480 + rowoff, pBhi);
        CP16(s0 + 20480 + rowoff + 16, pBhi + 16);
        CP16(s0 + 30720 + rowoff, pBlo);
        CP16(s0 + 30720 + rowoff + 16, pBlo + 16);
        if (MODE == 0) {
#pragma unroll
            for (int q = 0; q < 4; q++)
                *(float4*)(a32 + q * 4) = *(const float4*)(pA32 + q * 4);
        } else {
            CP16(s0 + rowoff, pAhi);
            CP16(s0 + rowoff + 16, pAhi + 16);
            CP16(s0 + 10240 + rowoff, pAlo);
            CP16(s0 + 10240 + rowoff + 16, pAlo + 16);
        }
        CPCOMMIT();
    }

    for (int it = 0; it < 16; it++) {
        uint32_t sbase = sb + (uint32_t)(it & 1) * G_STAGE;
        uint32_t nbase = sb + (uint32_t)((it + 1) & 1) * G_STAGE;

        if (MODE == 0) {
            // split + store A tile `it` (regs loaded last iter)
            uint32_t hv[8], lv[8];
#pragma unroll
            for (int q = 0; q < 8; q++) split_pack2(a32[q * 2], a32[q * 2 + 1], hv[q], lv[q]);
            *(uint4*)(smraw + (sbase - sb) + rowoff) = *(uint4*)&hv[0];
            *(uint4*)(smraw + (sbase - sb) + rowoff + 16) = *(uint4*)&hv[4];
            *(uint4*)(smraw + (sbase - sb) + 10240 + rowoff) = *(uint4*)&lv[0];
            *(uint4*)(smraw + (sbase - sb) + 10240 + rowoff + 16) = *(uint4*)&lv[4];
        }
        if (it + 1 < 16) {
            int ko = (it + 1) * 32;
            CP16(nbase + 20480 + rowoff, pBhi + ko * 2);
            CP16(nbase + 20480 + rowoff + 16, pBhi + ko * 2 + 16);
            CP16(nbase + 30720 + rowoff, pBlo + ko * 2);
            CP16(nbase + 30720 + rowoff + 16, pBlo + ko * 2 + 16);
            if (MODE == 0) {
#pragma unroll
                for (int q = 0; q < 4; q++)
                    *(float4*)(a32 + q * 4) = *(const float4*)(pA32 + ko + q * 4);
            } else {
                CP16(nbase + rowoff, pAhi + ko * 2);
                CP16(nbase + rowoff + 16, pAhi + ko * 2 + 16);
                CP16(nbase + 10240 + rowoff, pAlo + ko * 2);
                CP16(nbase + 10240 + rowoff + 16, pAlo + ko * 2 + 16);
            }
        }
        CPCOMMIT();
        CPWAIT1();
        __syncthreads();

        // ---- compute on stage sbase ----
#pragma unroll
        for (int kc = 0; kc < 2; kc++) {
            uint32_t ah[2][4], al[2][4];
#pragma unroll
            for (int mb = 0; mb < 2; mb++) {
                uint32_t ad = sbase +
                    ((wm * 32 + mb * 16 + (lane & 15)) * 40 + kc * 16 + (lane >> 4) * 8) * 2;
                LDSM4(ah[mb][0], ah[mb][1], ah[mb][2], ah[mb][3], ad);
                LDSM4(al[mb][0], al[mb][1], al[mb][2], al[mb][3], ad + 10240);
            }
#pragma unroll
            for (int jp = 0; jp < 4; jp++) {
                uint32_t bd = sbase + 20480 +
                    ((wn * 64 + jp * 16 + (lane & 7) + ((lane >> 3) & 1) * 8) * 40 +
                     kc * 16 + (lane >> 4) * 8) * 2;
                uint32_t bh[4], bl[4];
                LDSM4(bh[0], bh[1], bh[2], bh[3], bd);
                LDSM4(bl[0], bl[1], bl[2], bl[3], bd + 10240);
#pragma unroll
                for (int mb = 0; mb < 2; mb++) {
                    float* c0 = acc[mb * 8 + jp * 2];
                    float* c1 = acc[mb * 8 + jp * 2 + 1];
                    mma16816(c0, ah[mb], bh[0], bh[2]);
                    mma16816(c0, al[mb], bh[0], bh[2]);
                    mma16816(c0, ah[mb], bl[0], bl[2]);
                    mma16816(c1, ah[mb], bh[1], bh[3]);
                    mma16816(c1, al[mb], bh[1], bh[3]);
                    mma16816(c1, ah[mb], bl[1], bl[3]);
                }
            }
        }
        __syncthreads();
    }

    // ---------------- epilogue ----------------
#pragma unroll
    for (int mb = 0; mb < 2; mb++) {
        int gm0 = m0 + wm * 32 + mb * 16 + qr;
#pragma unroll
        for (int half = 0; half < 2; half++) {
            int gm = gm0 + half * 8;
            if (gm >= MROWS) continue;
            int bb = gm / NTOK;
            int nn = gm - bb * NTOK;
#pragma unroll
            for (int j = 0; j < 8; j++) {
                int col = n0 + wn * 64 + j * 8 + qc2;
                float v0 = acc[mb * 8 + j][half * 2 + 0];
                float v1 = acc[mb * 8 + j][half * 2 + 1];
                float2 bv = *(const float2*)(bias + col);
                v0 += bv.x;
                v1 += bv.y;
                if (MODE == 0) {
                    int s = col >> 9, hh = (col >> 5) & 15, d = col & 31;
                    if (s == 0) { v0 *= QK_SCALE; v1 *= QK_SCALE; }
                    uint32_t hi, lo;
                    split_pack2(v0, v1, hi, lo);
                    size_t idx = ((size_t)((bb * NH + hh) * NTOK + nn)) * HD + d;
                    __nv_bfloat16 *ph, *pl;
                    if (s == 0)      { ph = g_q_hi; pl = g_q_lo; }
                    else if (s == 1) { ph = g_k_hi; pl = g_k_lo; }
                    else             { ph = g_v_hi; pl = g_v_lo; }
                    *(uint32_t*)(ph + idx) = hi;
                    *(uint32_t*)(pl + idx) = lo;
                } else {
                    float2 o = make_float2(v0, v1);
                    *(float2*)(out + (size_t)gm * CDIM + col) = o;
                }
            }
        }
    }
}

// =====================================================================
// HMMA flash attention, cp.async double-buffered K/V.
// smem (bytes): stage s at s*40960: Khi 0 | Klo 10240 | Vhi 20480 | Vlo 30720
//               Qhi 81920 | Qlo 92160 ; total 102400
// =====================================================================
#define A_STAGE 40960
#define A_QOFF 81920
#define ATT_SMEM_BYTES 102400

__global__ void __launch_bounds__(256) attn_mma_kernel()
{
    extern __shared__ __align__(16) char smraw[];
    uint32_t sb = smem_u32(smraw);

    int b = blockIdx.z, h = blockIdx.y, q0 = blockIdx.x * 128;
    int tid = threadIdx.x, lane = tid & 31, wid = tid >> 5;
    int qr = lane >> 2, qc2 = (lane & 3) * 2;
    size_t ho = (size_t)((b * NH + h) * NTOK) * HD;

    int r = tid >> 1;
    int e0 = (tid & 1) * 16;
    uint32_t rowoff = (uint32_t)(r * 40 + e0) * 2;

    // ---- prologue: Q + KV tile 0 in one group ----
    {
        int gq = imin(q0 + r, NTOK - 1);
        const char* qh = (const char*)(g_q_hi + ho + (size_t)gq * HD + e0);
        const char* ql = (const char*)(g_q_lo + ho + (size_t)gq * HD + e0);
        CP16(sb + A_QOFF + rowoff, qh);
        CP16(sb + A_QOFF + rowoff + 16, qh + 16);
        CP16(sb + A_QOFF + 10240 + rowoff, ql);
        CP16(sb + A_QOFF + 10240 + rowoff + 16, ql + 16);
        int gk = imin(r, NTOK - 1);
        const char* kh = (const char*)(g_k_hi + ho + (size_t)gk * HD + e0);
        const char* kl = (const char*)(g_k_lo + ho + (size_t)gk * HD + e0);
        const char* vh = (const char*)(g_v_hi + ho + (size_t)gk * HD + e0);
        const char* vl = (const char*)(g_v_lo + ho + (size_t)gk * HD + e0);
        CP16(sb + rowoff, kh);
        CP16(sb + rowoff + 16, kh + 16);
        CP16(sb + 10240 + rowoff, kl);
        CP16(sb + 10240 + rowoff + 16, kl + 16);
        CP16(sb + 20480 + rowoff, vh);
        CP16(sb + 20480 + rowoff + 16, vh + 16);
        CP16(sb + 30720 + rowoff, vl);
        CP16(sb + 30720 + rowoff + 16, vl + 16);
        CPCOMMIT();
    }

    uint32_t qh[2][4], ql[2][4];
    float O[4][4];
#pragma unroll
    for (int i = 0; i < 4; i++)
#pragma unroll
        for (int j = 0; j < 4; j++) O[i][j] = 0.f;
    float mrow0 = -1e30f, mrow1 = -1e30f, lrow0 = 0.f, lrow1 = 0.f;

    int row0 = q0 + wid * 16 + qr;
    const float* bias0 = g_bias + ((size_t)h * NTOK + imin(row0, NTOK - 1)) * NTOK;
    const float* bias1 = g_bias + ((size_t)h * NTOK + imin(row0 + 8, NTOK - 1)) * NTOK;

    for (int kt = 0; kt < 6; kt++) {
        uint32_t sbase = sb + (uint32_t)(kt & 1) * A_STAGE;
        uint32_t nbase = sb + (uint32_t)((kt + 1) & 1) * A_STAGE;
        if (kt + 1 < 6) {
            int gk = imin((kt + 1) * 128 + r, NTOK - 1);
            const char* kh_ = (const char*)(g_k_hi + ho + (size_t)gk * HD + e0);
            const char* kl_ = (const char*)(g_k_lo + ho + (size_t)gk * HD + e0);
            const char* vh_ = (const char*)(g_v_hi + ho + (size_t)gk * HD + e0);
            const char* vl_ = (const char*)(g_v_lo + ho + (size_t)gk * HD + e0);
            CP16(nbase + rowoff, kh_);
            CP16(nbase + rowoff + 16, kh_ + 16);
            CP16(nbase + 10240 + rowoff, kl_);
            CP16(nbase + 10240 + rowoff + 16, kl_ + 16);
            CP16(nbase + 20480 + rowoff, vh_);
            CP16(nbase + 20480 + rowoff + 16, vh_ + 16);
            CP16(nbase + 30720 + rowoff, vl_);
            CP16(nbase + 30720 + rowoff + 16, vl_ + 16);
        }
        CPCOMMIT();
        CPWAIT1();
        __syncthreads();

        if (kt == 0) {
            // build Q fragments once (held in regs for all key tiles)
#pragma unroll
            for (int kc = 0; kc < 2; kc++) {
                uint32_t ad = sb + A_QOFF +
                    ((wid * 16 + (lane & 15)) * 40 + kc * 16 + (lane >> 4) * 8) * 2;
                LDSM4(qh[kc][0], qh[kc][1], qh[kc][2], qh[kc][3], ad);
                LDSM4(ql[kc][0], ql[kc][1], ql[kc][2], ql[kc][3], ad + 10240);
            }
        }

        int k0 = kt * 128;

        // ---- S = Q K^T (3-term split) ----
        float S[16][4];
#pragma unroll
        for (int i = 0; i < 16; i++)
#pragma unroll
            for (int j = 0; j < 4; j++) S[i][j] = 0.f;

#pragma unroll
        for (int kc = 0; kc < 2; kc++) {
#pragma unroll
            for (int jp = 0; jp < 8; jp++) {
                uint32_t bd = sbase +
                    ((jp * 16 + (lane & 7) + ((lane >> 3) & 1) * 8) * 40 +
                     kc * 16 + (lane >> 4) * 8) * 2;
                uint32_t bh[4], bl[4];
                LDSM4(bh[0], bh[1], bh[2], bh[3], bd);
                LDSM4(bl[0], bl[1], bl[2], bl[3], bd + 10240);
                float* c0 = S[jp * 2];
                float* c1 = S[jp * 2 + 1];
                mma16816(c0, qh[kc], bh[0], bh[2]);
                mma16816(c0, ql[kc], bh[0], bh[2]);
                mma16816(c0, qh[kc], bl[0], bl[2]);
                mma16816(c1, qh[kc], bh[1], bh[3]);
                mma16816(c1, ql[kc], bh[1], bh[3]);
                mma16816(c1, qh[kc], bl[1], bl[3]);
            }
        }

        // ---- bias + key mask ----
        int kv = NTOK - k0;
#pragma unroll
        for (int j = 0; j < 16; j++) {
            int c = j * 8 + qc2;
            float2 b0 = *(const float2*)(bias0 + k0 + c);
            float2 b1 = *(const float2*)(bias1 + k0 + c);
            S[j][0] += b0.x; S[j][1] += b0.y;
            S[j][2] += b1.x; S[j][3] += b1.y;
            if (c >= kv)     { S[j][0] = -1e30f; S[j][2] = -1e30f; }
            if (c + 1 >= kv) { S[j][1] = -1e30f; S[j][3] = -1e30f; }
        }

        // ---- online softmax ----
        float m0l = -1e30f, m1l = -1e30f;
#pragma unroll
        for (int j = 0; j < 16; j++) {
            m0l = fmaxf(m0l, fmaxf(S[j][0], S[j][1]));
            m1l = fmaxf(m1l, fmaxf(S[j][2], S[j][3]));
        }
        m0l = fmaxf(m0l, __shfl_xor_sync(0xffffffffu, m0l, 1));
        m0l = fmaxf(m0l, __shfl_xor_sync(0xffffffffu, m0l, 2));
        m1l = fmaxf(m1l, __shfl_xor_sync(0xffffffffu, m1l, 1));
        m1l = fmaxf(m1l, __shfl_xor_sync(0xffffffffu, m1l, 2));
        float mn0 = fmaxf(mrow0, m0l), mn1 = fmaxf(mrow1, m1l);
        float corr0 = __expf(mrow0 - mn0), corr1 = __expf(mrow1 - mn1);
        mrow0 = mn0; mrow1 = mn1;
        float s0 = 0.f, s1 = 0.f;
#pragma unroll
        for (int j = 0; j < 16; j++) {
            S[j][0] = __expf(S[j][0] - mn0); s0 += S[j][0];
            S[j][1] = __expf(S[j][1] - mn0); s0 += S[j][1];
            S[j][2] = __expf(S[j][2] - mn1); s1 += S[j][2];
            S[j][3] = __expf(S[j][3] - mn1); s1 += S[j][3];
        }
        s0 += __shfl_xor_sync(0xffffffffu, s0, 1);
        s0 += __shfl_xor_sync(0xffffffffu, s0, 2);
        s1 += __shfl_xor_sync(0xffffffffu, s1, 1);
        s1 += __shfl_xor_sync(0xffffffffu, s1, 2);
        lrow0 = lrow0 * corr0 + s0;
        lrow1 = lrow1 * corr1 + s1;
#pragma unroll
        for (int jd = 0; jd < 4; jd++) {
            O[jd][0] *= corr0; O[jd][1] *= corr0;
            O[jd][2] *= corr1; O[jd][3] *= corr1;
        }

        // ---- O += P V (split-bf16 x3) ----
#pragma unroll
        for (int kc = 0; kc < 8; kc++) {
            uint32_t pah[4], pal[4];
            split_pack2(S[2 * kc][0], S[2 * kc][1], pah[0], pal[0]);
            split_pack2(S[2 * kc][2], S[2 * kc][3], pah[1], pal[1]);
            split_pack2(S[2 * kc + 1][0], S[2 * kc + 1][1], pah[2], pal[2]);
            split_pack2(S[2 * kc + 1][2], S[2 * kc + 1][3], pah[3], pal[3]);
            uint32_t vrow = kc * 16 + (lane & 7) + ((lane >> 3) & 1) * 8;
            uint32_t vcb = (lane >> 4) * 8;
            uint32_t vd0 = sbase + 20480 + (vrow * 40 + vcb) * 2;
            uint32_t vd1 = sbase + 20480 + (vrow * 40 + 16 + vcb) * 2;
            uint32_t vh[8], vl[8];
            LDSM4T(vh[0], vh[1], vh[2], vh[3], vd0);
            LDSM4T(vh[4], vh[5], vh[6], vh[7], vd1);
            LDSM4T(vl[0], vl[1], vl[2], vl[3], vd0 + 10240);
            LDSM4T(vl[4], vl[5], vl[6], vl[7], vd1 + 10240);
            mma16816(O[0], pah, vh[0], vh[1]);
            mma16816(O[0], pal, vh[0], vh[1]);
            mma16816(O[0], pah, vl[0], vl[1]);
            mma16816(O[1], pah, vh[2], vh[3]);
            mma16816(O[1], pal, vh[2], vh[3]);
            mma16816(O[1], pah, vl[2], vl[3]);
            mma16816(O[2], pah, vh[4], vh[5]);
            mma16816(O[2], pal, vh[4], vh[5]);
            mma16816(O[2], pah, vl[4], vl[5]);
            mma16816(O[3], pah, vh[6], vh[7]);
            mma16816(O[3], pal, vh[6], vh[7]);
            mma16816(O[3], pah, vl[6], vl[7]);
        }
        __syncthreads();
    }

    // ---- output: normalize, split to bf16 hi/lo for proj GEMM ----
    float li0 = 1.f / lrow0, li1 = 1.f / lrow1;
#pragma unroll
    for (int jd = 0; jd < 4; jd++) {
        int d = jd * 8 + qc2;
        if (row0 < NTOK) {
            uint32_t hi, lo;
            split_pack2(O[jd][0] * li0, O[jd][1] * li0, hi, lo);
            size_t idx = ((size_t)(b * NTOK + row0)) * CDIM + h * HD + d;
            *(uint32_t*)(g_Ahi + idx) = hi;
            *(uint32_t*)(g_Alo + idx) = lo;
        }
        if (row0 + 8 < NTOK) {
            uint32_t hi, lo;
            split_pack2(O[jd][2] * li1, O[jd][3] * li1, hi, lo);
            size_t idx = ((size_t)(b * NTOK + row0 + 8)) * CDIM + h * HD + d;
            *(uint32_t*)(g_Ahi + idx) = hi;
            *(uint32_t*)(g_Alo + idx) = lo;
        }
    }
}

// =====================================================================
extern "C" void kernel_launch(void* const* d_in, const int* in_sizes, int n_in,
                              void* d_out, int out_size)
{
    const float* x    = (const float*)d_in[0];
    const float* Wqkv = (const float*)d_in[1];
    const float* bqkv = (const float*)d_in[2];
    const float* Wprj = (const float*)d_in[3];
    const float* bprj = (const float*)d_in[4];
    const float* btt  = (const float*)d_in[5];
    const float* btm  = (const float*)d_in[6];
    const float* ttt  = (const float*)d_in[7];
    const float* tgt  = (const float*)d_in[8];
    const float* ttl  = (const float*)d_in[9];
    const float* tgl  = (const float*)d_in[10];
    float* out = (float*)d_out;

    cudaFuncSetAttribute(attn_mma_kernel, cudaFuncAttributeMaxDynamicSharedMemorySize,
                         ATT_SMEM_BYTES);
    cudaFuncSetAttribute(gemm_mma_kernel<0>,
                         cudaFuncAttributeMaxDynamicSharedMemorySize, G_SMEM);
    cudaFuncSetAttribute(gemm_mma_kernel<1>,
                         cudaFuncAttributeMaxDynamicSharedMemorySize, G_SMEM);

    __nv_bfloat16 *pAhi, *pAlo, *pWhi, *pWlo, *pPhi, *pPlo;
    cudaGetSymbolAddress((void**)&pAhi, g_Ahi);
    cudaGetSymbolAddress((void**)&pAlo, g_Alo);
    cudaGetSymbolAddress((void**)&pWhi, g_Whi);
    cudaGetSymbolAddress((void**)&pWlo, g_Wlo);
    cudaGetSymbolAddress((void**)&pPhi, g_Phi);
    cudaGetSymbolAddress((void**)&pPlo, g_Plo);

    build_bias_kernel<<<dim3((NTOK * NTOK + 255) / 256, NH), 256>>>(
        btt, btm, ttt, tgt, ttl, tgl);
    tsplit_kernel<<<dim3(1536 / 32, 512 / 32), dim3(32, 8)>>>(Wqkv, pWhi, pWlo, 512, 1536);
    tsplit_kernel<<<dim3(512 / 32, 512 / 32), dim3(32, 8)>>>(Wprj, pPhi, pPlo, 512, 512);
    gemm_mma_kernel<0><<<dim3(12, 93), 256, G_SMEM>>>(
        x, nullptr, nullptr, pWhi, pWlo, bqkv, nullptr);
    attn_mma_kernel<<<dim3(6, NH, NB), 256, ATT_SMEM_BYTES>>>();
    gemm_mma_kernel<1><<<dim3(4, 93), 256, G_SMEM>>>(
        nullptr, pAhi, pAlo, pPhi, pPlo, bprj, out);
}

// round 10
// speedup vs baseline: 1.8446x; 1.8446x over previous
#include <cuda_runtime.h>
#include <cuda_bf16.h>
#include <cstdint>
#include <math.h>

#define NB 16
#define NH 16
#define NTOK 740
#define HD 32
#define CDIM 512
#define MROWS (NB * NTOK)            // 11840
#define BHND (NB * NH * NTOK * HD)   // 6062080
#define QK_SCALE 0.17677669529663687f

// ---------------- device scratch ----------------
__device__ __align__(16) float g_bias[NH * NTOK * NTOK + 256];
__device__ __align__(16) __nv_bfloat16 g_Ahi[MROWS * CDIM];   // x split / attn out
__device__ __align__(16) __nv_bfloat16 g_Alo[MROWS * CDIM];
__device__ __align__(16) __nv_bfloat16 g_Whi[3 * CDIM * CDIM]; // W_qkv^T [1536,512]
__device__ __align__(16) __nv_bfloat16 g_Wlo[3 * CDIM * CDIM];
__device__ __align__(16) __nv_bfloat16 g_Phi[CDIM * CDIM];     // W_proj^T [512,512]
__device__ __align__(16) __nv_bfloat16 g_Plo[CDIM * CDIM];
__device__ __align__(16) __nv_bfloat16 g_q_hi[BHND];
__device__ __align__(16) __nv_bfloat16 g_q_lo[BHND];
__device__ __align__(16) __nv_bfloat16 g_k_hi[BHND];
__device__ __align__(16) __nv_bfloat16 g_k_lo[BHND];
__device__ __align__(16) __nv_bfloat16 g_v_hi[BHND];
__device__ __align__(16) __nv_bfloat16 g_v_lo[BHND];

// ================= helpers (base-ISA only: mma.sync / ldmatrix) =================
__device__ __forceinline__ uint32_t smem_u32(const void* p) {
    uint32_t a;
    asm("{ .reg .u64 t; cvta.to.shared.u64 t, %1; cvt.u32.u64 %0, t; }" : "=r"(a) : "l"(p));
    return a;
}

__device__ __forceinline__ void mma16816(float c[4], const uint32_t a[4],
                                         uint32_t b0, uint32_t b1) {
    asm volatile(
        "mma.sync.aligned.m16n8k16.row.col.f32.bf16.bf16.f32 "
        "{%0,%1,%2,%3}, {%4,%5,%6,%7}, {%8,%9}, {%0,%1,%2,%3};"
        : "+f"(c[0]), "+f"(c[1]), "+f"(c[2]), "+f"(c[3])
        : "r"(a[0]), "r"(a[1]), "r"(a[2]), "r"(a[3]), "r"(b0), "r"(b1));
}

#define LDSM4(R0, R1, R2, R3, ADDR) \
    asm volatile("ldmatrix.sync.aligned.m8n8.x4.shared.b16 {%0,%1,%2,%3}, [%4];" \
        : "=r"(R0), "=r"(R1), "=r"(R2), "=r"(R3) : "r"(ADDR))

#define LDSM4T(R0, R1, R2, R3, ADDR) \
    asm volatile("ldmatrix.sync.aligned.m8n8.x4.trans.shared.b16 {%0,%1,%2,%3}, [%4];" \
        : "=r"(R0), "=r"(R1), "=r"(R2), "=r"(R3) : "r"(ADDR))

// split fp32 pair -> packed bf16 hi pair + lo (residual) pair
__device__ __forceinline__ void split_pack2(float f0, float f1,
                                            uint32_t& hi, uint32_t& lo) {
    __nv_bfloat16 h0 = __float2bfloat16(f0);
    __nv_bfloat16 h1 = __float2bfloat16(f1);
    __nv_bfloat162 hv(h0, h1);
    hi = *reinterpret_cast<uint32_t*>(&hv);
    __nv_bfloat162 lv(__float2bfloat16(f0 - __bfloat162float(h0)),
                      __float2bfloat16(f1 - __bfloat162float(h1)));
    lo = *reinterpret_cast<uint32_t*>(&lv);
}

__device__ __forceinline__ int imin(int a, int b) { return a < b ? a : b; }

// =====================================================================
// Bias assembly
// =====================================================================
__global__ void build_bias_kernel(const float* __restrict__ btt,
                                  const float* __restrict__ btm,
                                  const float* __restrict__ ttt,
                                  const float* __restrict__ tgt,
                                  const float* __restrict__ ttl,
                                  const float* __restrict__ tgl)
{
    int p = blockIdx.x * 256 + threadIdx.x;
    if (p >= NTOK * NTOK) return;
    int h = blockIdx.y;
    int i = p / NTOK, j = p - i * NTOK;
    float v;
    if (i < 256) {
        if (j < 256) {
            int ai = i >> 4, bi = i & 15, aj = j >> 4, bj = j & 15;
            int idx = (ai - aj + 15) * 31 + (bi - bj + 15);
            v = btm[idx * NH + h];
        } else {
            v = tgt[h * 256 + i] + tgl[h * 484 + (j - 256)];
        }
    } else {
        int i2 = i - 256;
        if (j < 256) {
            v = ttt[h * 484 + i2] + ttl[h * 256 + j];
        } else {
            int j2 = j - 256;
            int ai = i2 / 22, bi = i2 - ai * 22;
            int aj = j2 / 22, bj = j2 - aj * 22;
            int idx = (ai - aj + 21) * 43 + (bi - bj + 21);
            v = btt[idx * NH + h];
        }
    }
    g_bias[h * NTOK * NTOK + p] = v;
}

// =====================================================================
// fp32 -> (hi, lo) bf16 split, elementwise
// =====================================================================
__global__ void split_kernel(const float* __restrict__ in,
                             __nv_bfloat16* __restrict__ hi,
                             __nv_bfloat16* __restrict__ lo, int n4)
{
    int i = blockIdx.x * 256 + threadIdx.x;
    if (i >= n4) return;
    float4 v = ((const float4*)in)[i];
    uint32_t h0, l0, h1, l1;
    split_pack2(v.x, v.y, h0, l0);
    split_pack2(v.z, v.w, h1, l1);
    uint2* ph = (uint2*)hi;
    uint2* pl = (uint2*)lo;
    ph[i] = make_uint2(h0, h1);
    pl[i] = make_uint2(l0, l1);
}

// =====================================================================
// Transpose + split: W[K,NN] fp32 -> hi/lo[NN,K] bf16
// =====================================================================
__global__ void tsplit_kernel(const float* __restrict__ W,
                              __nv_bfloat16* __restrict__ hi,
                              __nv_bfloat16* __restrict__ lo, int K, int NN)
{
    __shared__ float t[32][33];
    int nb = blockIdx.x * 32, kb = blockIdx.y * 32;
    int tx = threadIdx.x, ty = threadIdx.y;
#pragma unroll
    for (int i = 0; i < 32; i += 8)
        t[ty + i][tx] = W[(size_t)(kb + ty + i) * NN + nb + tx];
    __syncthreads();
#pragma unroll
    for (int i = 0; i < 32; i += 8) {
        float v = t[tx][ty + i];
        __nv_bfloat16 h = __float2bfloat16(v);
        __nv_bfloat16 l = __float2bfloat16(v - __bfloat162float(h));
        size_t o = (size_t)(nb + ty + i) * K + kb + tx;
        hi[o] = h;
        lo[o] = l;
    }
}

// =====================================================================
// HMMA split-bf16 GEMM: C[128m x 128n] = A[.,512] @ B[.,512]^T (+bias)
// MODE 0: qkv epilogue -> q/k/v split-bf16 [B,H,N,hd], q scaled
// MODE 1: proj epilogue -> fp32 out
// 256 threads; warp grid 4m x 2n; warp tile 32m x 64n; 2 CTAs/SM forced
// =====================================================================
template <int MODE>
__global__ void __launch_bounds__(256, 2) gemm_mma_kernel(
    const __nv_bfloat16* __restrict__ Ahi, const __nv_bfloat16* __restrict__ Alo,
    const __nv_bfloat16* __restrict__ Bhi, const __nv_bfloat16* __restrict__ Blo,
    const float* __restrict__ bias, float* __restrict__ out)
{
    __shared__ __align__(16) __nv_bfloat16 sA[2][128 * 40];
    __shared__ __align__(16) __nv_bfloat16 sB[2][128 * 40];
    int tid = threadIdx.x, lane = tid & 31, wid = tid >> 5;
    int wm = wid >> 1, wn = wid & 1;
    int m0 = blockIdx.y * 128, n0 = blockIdx.x * 128;
    int qr = lane >> 2, qc2 = (lane & 3) * 2;

    float acc[16][4];
#pragma unroll
    for (int i = 0; i < 16; i++)
#pragma unroll
        for (int j = 0; j < 4; j++) acc[i][j] = 0.f;

    int r = tid >> 1, cb = (tid & 1) * 16;
    int arow = imin(m0 + r, MROWS - 1);
    int brow = n0 + r;
    const uint4* gA0 = (const uint4*)(Ahi + (size_t)arow * CDIM);
    const uint4* gA1 = (const uint4*)(Alo + (size_t)arow * CDIM);
    const uint4* gB0 = (const uint4*)(Bhi + (size_t)brow * CDIM);
    const uint4* gB1 = (const uint4*)(Blo + (size_t)brow * CDIM);
    uint32_t sAb = smem_u32(sA);
    uint32_t sBb = smem_u32(sB);

    for (int k0 = 0; k0 < CDIM; k0 += 32) {
        int kq = (k0 + cb) >> 3;
        uint4 va0 = gA0[kq], va0b = gA0[kq + 1];
        uint4 va1 = gA1[kq], va1b = gA1[kq + 1];
        uint4 vb0 = gB0[kq], vb0b = gB0[kq + 1];
        uint4 vb1 = gB1[kq], vb1b = gB1[kq + 1];
        if (k0) __syncthreads();
        *(uint4*)(&sA[0][r * 40 + cb]) = va0;
        *(uint4*)(&sA[0][r * 40 + cb + 8]) = va0b;
        *(uint4*)(&sA[1][r * 40 + cb]) = va1;
        *(uint4*)(&sA[1][r * 40 + cb + 8]) = va1b;
        *(uint4*)(&sB[0][r * 40 + cb]) = vb0;
        *(uint4*)(&sB[0][r * 40 + cb + 8]) = vb0b;
        *(uint4*)(&sB[1][r * 40 + cb]) = vb1;
        *(uint4*)(&sB[1][r * 40 + cb + 8]) = vb1b;
        __syncthreads();

#pragma unroll
        for (int kc = 0; kc < 2; kc++) {
            uint32_t ah[2][4], al[2][4];
#pragma unroll
            for (int mb = 0; mb < 2; mb++) {
                uint32_t ad = sAb +
                    ((wm * 32 + mb * 16 + (lane & 15)) * 40 + kc * 16 + (lane >> 4) * 8) * 2;
                LDSM4(ah[mb][0], ah[mb][1], ah[mb][2], ah[mb][3], ad);
                LDSM4(al[mb][0], al[mb][1], al[mb][2], al[mb][3], ad + 10240);
            }
#pragma unroll
            for (int jp = 0; jp < 4; jp++) {
                uint32_t bd = sBb +
                    ((wn * 64 + jp * 16 + (lane & 7) + ((lane >> 3) & 1) * 8) * 40 +
                     kc * 16 + (lane >> 4) * 8) * 2;
                uint32_t bh[4], bl[4];
                LDSM4(bh[0], bh[1], bh[2], bh[3], bd);
                LDSM4(bl[0], bl[1], bl[2], bl[3], bd + 10240);
#pragma unroll
                for (int mb = 0; mb < 2; mb++) {
                    float* c0 = acc[mb * 8 + jp * 2];
                    float* c1 = acc[mb * 8 + jp * 2 + 1];
                    mma16816(c0, ah[mb], bh[0], bh[2]);
                    mma16816(c0, al[mb], bh[0], bh[2]);
                    mma16816(c0, ah[mb], bl[0], bl[2]);
                    mma16816(c1, ah[mb], bh[1], bh[3]);
                    mma16816(c1, al[mb], bh[1], bh[3]);
                    mma16816(c1, ah[mb], bl[1], bl[3]);
                }
            }
        }
    }

    // ---------------- epilogue ----------------
#pragma unroll
    for (int mb = 0; mb < 2; mb++) {
        int gm0 = m0 + wm * 32 + mb * 16 + qr;
#pragma unroll
        for (int half = 0; half < 2; half++) {
            int gm = gm0 + half * 8;
            if (gm >= MROWS) continue;
            int bb = gm / NTOK;
            int nn = gm - bb * NTOK;
#pragma unroll
            for (int j = 0; j < 8; j++) {
                int col = n0 + wn * 64 + j * 8 + qc2;
                float v0 = acc[mb * 8 + j][half * 2 + 0];
                float v1 = acc[mb * 8 + j][half * 2 + 1];
                float2 bv = *(const float2*)(bias + col);
                v0 += bv.x;
                v1 += bv.y;
                if (MODE == 0) {
                    int s = col >> 9, hh = (col >> 5) & 15, d = col & 31;
                    if (s == 0) { v0 *= QK_SCALE; v1 *= QK_SCALE; }
                    uint32_t hi, lo;
                    split_pack2(v0, v1, hi, lo);
                    size_t idx = ((size_t)((bb * NH + hh) * NTOK + nn)) * HD + d;
                    __nv_bfloat16 *ph, *pl;
                    if (s == 0)      { ph = g_q_hi; pl = g_q_lo; }
                    else if (s == 1) { ph = g_k_hi; pl = g_k_lo; }
                    else             { ph = g_v_hi; pl = g_v_lo; }
                    *(uint32_t*)(ph + idx) = hi;
                    *(uint32_t*)(pl + idx) = lo;
                } else {
                    float2 o = make_float2(v0, v1);
                    *(float2*)(out + (size_t)gm * CDIM + col) = o;
                }
            }
        }
    }
}

// =====================================================================
// HMMA flash attention: q-tile 128 x key-tile 128, hd=32, split-bf16 x3
// grid (6, NH, NB), 256 threads (8 warps, 16 q-rows each); 2 CTAs/SM forced
// =====================================================================
#define ATT_SMEM_BYTES (3 * 2 * 128 * 40 * 2)   // Q,K,V x (hi,lo) x 128x40 bf16 = 61440

__global__ void __launch_bounds__(256, 2) attn_mma_kernel()
{
    extern __shared__ __align__(16) __nv_bfloat16 smA[];
    __nv_bfloat16* sQ = smA;               // hi at +0, lo at +5120 elems
    __nv_bfloat16* sK = smA + 10240;
    __nv_bfloat16* sV = smA + 20480;
    uint32_t sQb = smem_u32(sQ);
    uint32_t sKb = smem_u32(sK);
    uint32_t sVb = smem_u32(sV);

    int b = blockIdx.z, h = blockIdx.y, q0 = blockIdx.x * 128;
    int tid = threadIdx.x, lane = tid & 31, wid = tid >> 5;
    int qr = lane >> 2, qc2 = (lane & 3) * 2;
    size_t ho = (size_t)((b * NH + h) * NTOK) * HD;

    // load Q tile (hi+lo), rows clamped
    {
        int r = tid >> 1, cb = (tid & 1) * 16, ci = cb >> 3;
        int gr = imin(q0 + r, NTOK - 1);
        const uint4* s0 = (const uint4*)(g_q_hi + ho + (size_t)gr * HD);
        const uint4* s1 = (const uint4*)(g_q_lo + ho + (size_t)gr * HD);
        *(uint4*)(sQ + r * 40 + cb) = s0[ci];
        *(uint4*)(sQ + r * 40 + cb + 8) = s0[ci + 1];
        *(uint4*)(sQ + 5120 + r * 40 + cb) = s1[ci];
        *(uint4*)(sQ + 5120 + r * 40 + cb + 8) = s1[ci + 1];
    }
    __syncthreads();

    // Q fragments, kept in registers for all 6 key tiles
    uint32_t qh[2][4], ql[2][4];
#pragma unroll
    for (int kc = 0; kc < 2; kc++) {
        uint32_t ad = sQb + ((wid * 16 + (lane & 15)) * 40 + kc * 16 + (lane >> 4) * 8) * 2;
        LDSM4(qh[kc][0], qh[kc][1], qh[kc][2], qh[kc][3], ad);
        LDSM4(ql[kc][0], ql[kc][1], ql[kc][2], ql[kc][3], ad + 10240);
    }

    float O[4][4];
#pragma unroll
    for (int i = 0; i < 4; i++)
#pragma unroll
        for (int j = 0; j < 4; j++) O[i][j] = 0.f;
    float mrow0 = -1e30f, mrow1 = -1e30f, lrow0 = 0.f, lrow1 = 0.f;

    int row0 = q0 + wid * 16 + qr;           // global q row (within batch-head)
    const float* bias0 = g_bias + ((size_t)h * NTOK + imin(row0, NTOK - 1)) * NTOK;
    const float* bias1 = g_bias + ((size_t)h * NTOK + imin(row0 + 8, NTOK - 1)) * NTOK;

    for (int kt = 0; kt < 6; kt++) {
        int k0 = kt * 128;
        if (kt) __syncthreads();
        // load K, V tiles (hi+lo)
        {
            int r = tid >> 1, cb = (tid & 1) * 16, ci = cb >> 3;
            int gr = imin(k0 + r, NTOK - 1);
            const uint4* kh = (const uint4*)(g_k_hi + ho + (size_t)gr * HD);
            const uint4* kl = (const uint4*)(g_k_lo + ho + (size_t)gr * HD);
            const uint4* vh = (const uint4*)(g_v_hi + ho + (size_t)gr * HD);
            const uint4* vl = (const uint4*)(g_v_lo + ho + (size_t)gr * HD);
            *(uint4*)(sK + r * 40 + cb) = kh[ci];
            *(uint4*)(sK + r * 40 + cb + 8) = kh[ci + 1];
            *(uint4*)(sK + 5120 + r * 40 + cb) = kl[ci];
            *(uint4*)(sK + 5120 + r * 40 + cb + 8) = kl[ci + 1];
            *(uint4*)(sV + r * 40 + cb) = vh[ci];
            *(uint4*)(sV + r * 40 + cb + 8) = vh[ci + 1];
            *(uint4*)(sV + 5120 + r * 40 + cb) = vl[ci];
            *(uint4*)(sV + 5120 + r * 40 + cb + 8) = vl[ci + 1];
        }
        __syncthreads();

        // ---- S = Q K^T (3-term split) ----
        float S[16][4];
#pragma unroll
        for (int i = 0; i < 16; i++)
#pragma unroll
            for (int j = 0; j < 4; j++) S[i][j] = 0.f;

#pragma unroll
        for (int kc = 0; kc < 2; kc++) {
#pragma unroll
            for (int jp = 0; jp < 8; jp++) {
                uint32_t bd = sKb +
                    ((jp * 16 + (lane & 7) + ((lane >> 3) & 1) * 8) * 40 +
                     kc * 16 + (lane >> 4) * 8) * 2;
                uint32_t bh[4], bl[4];
                LDSM4(bh[0], bh[1], bh[2], bh[3], bd);
                LDSM4(bl[0], bl[1], bl[2], bl[3], bd + 10240);
                float* c0 = S[jp * 2];
                float* c1 = S[jp * 2 + 1];
                mma16816(c0, qh[kc], bh[0], bh[2]);
                mma16816(c0, ql[kc], bh[0], bh[2]);
                mma16816(c0, qh[kc], bl[0], bl[2]);
                mma16816(c1, qh[kc], bh[1], bh[3]);
                mma16816(c1, ql[kc], bh[1], bh[3]);
                mma16816(c1, qh[kc], bl[1], bl[3]);
            }
        }

        // ---- bias + key mask ----
        int kv = NTOK - k0;
#pragma unroll
        for (int j = 0; j < 16; j++) {
            int c = j * 8 + qc2;
            float2 b0 = *(const float2*)(bias0 + k0 + c);
            float2 b1 = *(const float2*)(bias1 + k0 + c);
            S[j][0] += b0.x; S[j][1] += b0.y;
            S[j][2] += b1.x; S[j][3] += b1.y;
            if (c >= kv)     { S[j][0] = -1e30f; S[j][2] = -1e30f; }
            if (c + 1 >= kv) { S[j][1] = -1e30f; S[j][3] = -1e30f; }
        }

        // ---- online softmax ----
        float m0l = -1e30f, m1l = -1e30f;
#pragma unroll
        for (int j = 0; j < 16; j++) {
            m0l = fmaxf(m0l, fmaxf(S[j][0], S[j][1]));
            m1l = fmaxf(m1l, fmaxf(S[j][2], S[j][3]));
        }
        m0l = fmaxf(m0l, __shfl_xor_sync(0xffffffffu, m0l, 1));
        m0l = fmaxf(m0l, __shfl_xor_sync(0xffffffffu, m0l, 2));
        m1l = fmaxf(m1l, __shfl_xor_sync(0xffffffffu, m1l, 1));
        m1l = fmaxf(m1l, __shfl_xor_sync(0xffffffffu, m1l, 2));
        float mn0 = fmaxf(mrow0, m0l), mn1 = fmaxf(mrow1, m1l);
        float corr0 = __expf(mrow0 - mn0), corr1 = __expf(mrow1 - mn1);
        mrow0 = mn0; mrow1 = mn1;
        float s0 = 0.f, s1 = 0.f;
#pragma unroll
        for (int j = 0; j < 16; j++) {
            S[j][0] = __expf(S[j][0] - mn0); s0 += S[j][0];
            S[j][1] = __expf(S[j][1] - mn0); s0 += S[j][1];
            S[j][2] = __expf(S[j][2] - mn1); s1 += S[j][2];
            S[j][3] = __expf(S[j][3] - mn1); s1 += S[j][3];
        }
        s0 += __shfl_xor_sync(0xffffffffu, s0, 1);
        s0 += __shfl_xor_sync(0xffffffffu, s0, 2);
        s1 += __shfl_xor_sync(0xffffffffu, s1, 1);
        s1 += __shfl_xor_sync(0xffffffffu, s1, 2);
        lrow0 = lrow0 * corr0 + s0;
        lrow1 = lrow1 * corr1 + s1;
#pragma unroll
        for (int jd = 0; jd < 4; jd++) {
            O[jd][0] *= corr0; O[jd][1] *= corr0;
            O[jd][2] *= corr1; O[jd][3] *= corr1;
        }

        // ---- O += P V (P from S fragments, split-bf16 x3) ----
#pragma unroll
        for (int kc = 0; kc < 8; kc++) {
            uint32_t pah[4], pal[4];
            split_pack2(S[2 * kc][0], S[2 * kc][1], pah[0], pal[0]);
            split_pack2(S[2 * kc][2], S[2 * kc][3], pah[1], pal[1]);
            split_pack2(S[2 * kc + 1][0], S[2 * kc + 1][1], pah[2], pal[2]);
            split_pack2(S[2 * kc + 1][2], S[2 * kc + 1][3], pah[3], pal[3]);
            uint32_t vrow = kc * 16 + (lane & 7) + ((lane >> 3) & 1) * 8;
            uint32_t vcb = (lane >> 4) * 8;
            uint32_t vd0 = sVb + (vrow * 40 + vcb) * 2;
            uint32_t vd1 = sVb + (vrow * 40 + 16 + vcb) * 2;
            uint32_t vh[8], vl[8];
            LDSM4T(vh[0], vh[1], vh[2], vh[3], vd0);
            LDSM4T(vh[4], vh[5], vh[6], vh[7], vd1);
            LDSM4T(vl[0], vl[1], vl[2], vl[3], vd0 + 10240);
            LDSM4T(vl[4], vl[5], vl[6], vl[7], vd1 + 10240);
            mma16816(O[0], pah, vh[0], vh[1]);
            mma16816(O[0], pal, vh[0], vh[1]);
            mma16816(O[0], pah, vl[0], vl[1]);
            mma16816(O[1], pah, vh[2], vh[3]);
            mma16816(O[1], pal, vh[2], vh[3]);
            mma16816(O[1], pah, vl[2], vl[3]);
            mma16816(O[2], pah, vh[4], vh[5]);
            mma16816(O[2], pal, vh[4], vh[5]);
            mma16816(O[2], pah, vl[4], vl[5]);
            mma16816(O[3], pah, vh[6], vh[7]);
            mma16816(O[3], pal, vh[6], vh[7]);
            mma16816(O[3], pah, vl[6], vl[7]);
        }
    }

    // ---- output: normalize, split to bf16 hi/lo for proj GEMM ----
    float li0 = 1.f / lrow0, li1 = 1.f / lrow1;
#pragma unroll
    for (int jd = 0; jd < 4; jd++) {
        int d = jd * 8 + qc2;
        if (row0 < NTOK) {
            uint32_t hi, lo;
            split_pack2(O[jd][0] * li0, O[jd][1] * li0, hi, lo);
            size_t idx = ((size_t)(b * NTOK + row0)) * CDIM + h * HD + d;
            *(uint32_t*)(g_Ahi + idx) = hi;
            *(uint32_t*)(g_Alo + idx) = lo;
        }
        if (row0 + 8 < NTOK) {
            uint32_t hi, lo;
            split_pack2(O[jd][2] * li1, O[jd][3] * li1, hi, lo);
            size_t idx = ((size_t)(b * NTOK + row0 + 8)) * CDIM + h * HD + d;
            *(uint32_t*)(g_Ahi + idx) = hi;
            *(uint32_t*)(g_Alo + idx) = lo;
        }
    }
}

// =====================================================================
extern "C" void kernel_launch(void* const* d_in, const int* in_sizes, int n_in,
                              void* d_out, int out_size)
{
    const float* x    = (const float*)d_in[0];
    const float* Wqkv = (const float*)d_in[1];
    const float* bqkv = (const float*)d_in[2];
    const float* Wprj = (const float*)d_in[3];
    const float* bprj = (const float*)d_in[4];
    const float* btt  = (const float*)d_in[5];
    const float* btm  = (const float*)d_in[6];
    const float* ttt  = (const float*)d_in[7];
    const float* tgt  = (const float*)d_in[8];
    const float* ttl  = (const float*)d_in[9];
    const float* tgl  = (const float*)d_in[10];
    float* out = (float*)d_out;

    cudaFuncSetAttribute(attn_mma_kernel, cudaFuncAttributeMaxDynamicSharedMemorySize,
                         ATT_SMEM_BYTES);

    __nv_bfloat16 *pAhi, *pAlo, *pWhi, *pWlo, *pPhi, *pPlo;
    cudaGetSymbolAddress((void**)&pAhi, g_Ahi);
    cudaGetSymbolAddress((void**)&pAlo, g_Alo);
    cudaGetSymbolAddress((void**)&pWhi, g_Whi);
    cudaGetSymbolAddress((void**)&pWlo, g_Wlo);
    cudaGetSymbolAddress((void**)&pPhi, g_Phi);
    cudaGetSymbolAddress((void**)&pPlo, g_Plo);

    const int n4 = MROWS * CDIM / 4;

    build_bias_kernel<<<dim3((NTOK * NTOK + 255) / 256, NH), 256>>>(
        btt, btm, ttt, tgt, ttl, tgl);
    split_kernel<<<(n4 + 255) / 256, 256>>>(x, pAhi, pAlo, n4);
    tsplit_kernel<<<dim3(1536 / 32, 512 / 32), dim3(32, 8)>>>(Wqkv, pWhi, pWlo, 512, 1536);
    tsplit_kernel<<<dim3(512 / 32, 512 / 32), dim3(32, 8)>>>(Wprj, pPhi, pPlo, 512, 512);
    gemm_mma_kernel<0><<<dim3(12, 93), 256>>>(pAhi, pAlo, pWhi, pWlo, bqkv, nullptr);
    attn_mma_kernel<<<dim3(6, NH, NB), 256, ATT_SMEM_BYTES>>>();
    gemm_mma_kernel<1><<<dim3(4, 93), 256>>>(pAhi, pAlo, pPhi, pPlo, bprj, out);
}

// round 13
// speedup vs baseline: 1.9954x; 1.0818x over previous
#include <cuda_runtime.h>
#include <cuda_bf16.h>
#include <cuda_fp16.h>
#include <cstdint>
#include <math.h>

#define NB 16
#define NH 16
#define NTOK 740
#define HD 32
#define CDIM 512
#define MROWS (NB * NTOK)            // 11840
#define BHND (NB * NH * NTOK * HD)   // 6062080
#define QK_SCALE 0.17677669529663687f

// ---------------- device scratch ----------------
__device__ __align__(16) __nv_bfloat16 g_biasb[NH * NTOK * NTOK + 256];
__device__ __align__(16) __nv_bfloat16 g_Ahi[MROWS * CDIM];   // x split / attn out
__device__ __align__(16) __nv_bfloat16 g_Alo[MROWS * CDIM];
__device__ __align__(16) __nv_bfloat16 g_Whi[3 * CDIM * CDIM]; // W_qkv^T [1536,512]
__device__ __align__(16) __nv_bfloat16 g_Wlo[3 * CDIM * CDIM];
__device__ __align__(16) __nv_bfloat16 g_Phi[CDIM * CDIM];     // W_proj^T [512,512]
__device__ __align__(16) __nv_bfloat16 g_Plo[CDIM * CDIM];
__device__ __align__(16) __nv_bfloat16 g_q_hi[BHND];
__device__ __align__(16) __nv_bfloat16 g_q_lo[BHND];
__device__ __align__(16) __nv_bfloat16 g_k_hi[BHND];
__device__ __align__(16) __nv_bfloat16 g_k_lo[BHND];
__device__ __align__(16) __half g_v_hi[BHND];                  // V in fp16 split
__device__ __align__(16) __half g_v_lo[BHND];

// ================= helpers (base-ISA only: mma.sync / ldmatrix) =================
__device__ __forceinline__ uint32_t smem_u32(const void* p) {
    uint32_t a;
    asm("{ .reg .u64 t; cvta.to.shared.u64 t, %1; cvt.u32.u64 %0, t; }" : "=r"(a) : "l"(p));
    return a;
}

__device__ __forceinline__ void mma16816(float c[4], const uint32_t a[4],
                                         uint32_t b0, uint32_t b1) {
    asm volatile(
        "mma.sync.aligned.m16n8k16.row.col.f32.bf16.bf16.f32 "
        "{%0,%1,%2,%3}, {%4,%5,%6,%7}, {%8,%9}, {%0,%1,%2,%3};"
        : "+f"(c[0]), "+f"(c[1]), "+f"(c[2]), "+f"(c[3])
        : "r"(a[0]), "r"(a[1]), "r"(a[2]), "r"(a[3]), "r"(b0), "r"(b1));
}

__device__ __forceinline__ void mma16816h(float c[4], const uint32_t a[4],
                                          uint32_t b0, uint32_t b1) {
    asm volatile(
        "mma.sync.aligned.m16n8k16.row.col.f32.f16.f16.f32 "
        "{%0,%1,%2,%3}, {%4,%5,%6,%7}, {%8,%9}, {%0,%1,%2,%3};"
        : "+f"(c[0]), "+f"(c[1]), "+f"(c[2]), "+f"(c[3])
        : "r"(a[0]), "r"(a[1]), "r"(a[2]), "r"(a[3]), "r"(b0), "r"(b1));
}

#define LDSM4(R0, R1, R2, R3, ADDR) \
    asm volatile("ldmatrix.sync.aligned.m8n8.x4.shared.b16 {%0,%1,%2,%3}, [%4];" \
        : "=r"(R0), "=r"(R1), "=r"(R2), "=r"(R3) : "r"(ADDR))

#define LDSM4T(R0, R1, R2, R3, ADDR) \
    asm volatile("ldmatrix.sync.aligned.m8n8.x4.trans.shared.b16 {%0,%1,%2,%3}, [%4];" \
        : "=r"(R0), "=r"(R1), "=r"(R2), "=r"(R3) : "r"(ADDR))

// split fp32 pair -> packed bf16 hi pair + lo (residual) pair
__device__ __forceinline__ void split_pack2(float f0, float f1,
                                            uint32_t& hi, uint32_t& lo) {
    __nv_bfloat16 h0 = __float2bfloat16(f0);
    __nv_bfloat16 h1 = __float2bfloat16(f1);
    __nv_bfloat162 hv(h0, h1);
    hi = *reinterpret_cast<uint32_t*>(&hv);
    __nv_bfloat162 lv(__float2bfloat16(f0 - __bfloat162float(h0)),
                      __float2bfloat16(f1 - __bfloat162float(h1)));
    lo = *reinterpret_cast<uint32_t*>(&lv);
}

// split fp32 pair -> packed fp16 hi pair + lo (residual) pair
__device__ __forceinline__ void split_pack2h(float f0, float f1,
                                             uint32_t& hi, uint32_t& lo) {
    __half h0 = __float2half_rn(f0);
    __half h1 = __float2half_rn(f1);
    __half2 hv = __halves2half2(h0, h1);
    hi = *reinterpret_cast<uint32_t*>(&hv);
    __half2 lv = __halves2half2(__float2half_rn(f0 - __half2float(h0)),
                                __float2half_rn(f1 - __half2float(h1)));
    lo = *reinterpret_cast<uint32_t*>(&lv);
}

__device__ __forceinline__ uint32_t pack_h2(float f0, float f1) {
    __half2 h = __floats2half2_rn(f0, f1);
    return *reinterpret_cast<uint32_t*>(&h);
}

__device__ __forceinline__ int imin(int a, int b) { return a < b ? a : b; }

// =====================================================================
// Bias assembly (bf16 output)
// =====================================================================
__global__ void build_bias_kernel(const float* __restrict__ btt,
                                  const float* __restrict__ btm,
                                  const float* __restrict__ ttt,
                                  const float* __restrict__ tgt,
                                  const float* __restrict__ ttl,
                                  const float* __restrict__ tgl)
{
    int p = blockIdx.x * 256 + threadIdx.x;
    if (p >= NTOK * NTOK) return;
    int h = blockIdx.y;
    int i = p / NTOK, j = p - i * NTOK;
    float v;
    if (i < 256) {
        if (j < 256) {
            int ai = i >> 4, bi = i & 15, aj = j >> 4, bj = j & 15;
            int idx = (ai - aj + 15) * 31 + (bi - bj + 15);
            v = btm[idx * NH + h];
        } else {
            v = tgt[h * 256 + i] + tgl[h * 484 + (j - 256)];
        }
    } else {
        int i2 = i - 256;
        if (j < 256) {
            v = ttt[h * 484 + i2] + ttl[h * 256 + j];
        } else {
            int j2 = j - 256;
            int ai = i2 / 22, bi = i2 - ai * 22;
            int aj = j2 / 22, bj = j2 - aj * 22;
            int idx = (ai - aj + 21) * 43 + (bi - bj + 21);
            v = btt[idx * NH + h];
        }
    }
    g_biasb[h * NTOK * NTOK + p] = __float2bfloat16(v);
}

// =====================================================================
// fp32 -> (hi, lo) bf16 split, elementwise
// =====================================================================
__global__ void split_kernel(const float* __restrict__ in,
                             __nv_bfloat16* __restrict__ hi,
                             __nv_bfloat16* __restrict__ lo, int n4)
{
    int i = blockIdx.x * 256 + threadIdx.x;
    if (i >= n4) return;
    float4 v = ((const float4*)in)[i];
    uint32_t h0, l0, h1, l1;
    split_pack2(v.x, v.y, h0, l0);
    split_pack2(v.z, v.w, h1, l1);
    uint2* ph = (uint2*)hi;
    uint2* pl = (uint2*)lo;
    ph[i] = make_uint2(h0, h1);
    pl[i] = make_uint2(l0, l1);
}

// =====================================================================
// Transpose + split: W[K,NN] fp32 -> hi/lo[NN,K] bf16
// =====================================================================
__global__ void tsplit_kernel(const float* __restrict__ W,
                              __nv_bfloat16* __restrict__ hi,
                              __nv_bfloat16* __restrict__ lo, int K, int NN)
{
    __shared__ float t[32][33];
    int nb = blockIdx.x * 32, kb = blockIdx.y * 32;
    int tx = threadIdx.x, ty = threadIdx.y;
#pragma unroll
    for (int i = 0; i < 32; i += 8)
        t[ty + i][tx] = W[(size_t)(kb + ty + i) * NN + nb + tx];
    __syncthreads();
#pragma unroll
    for (int i = 0; i < 32; i += 8) {
        float v = t[tx][ty + i];
        __nv_bfloat16 h = __float2bfloat16(v);
        __nv_bfloat16 l = __float2bfloat16(v - __bfloat162float(h));
        size_t o = (size_t)(nb + ty + i) * K + kb + tx;
        hi[o] = h;
        lo[o] = l;
    }
}

// =====================================================================
// HMMA split-bf16 GEMM: C[128m x 128n] = A[.,512] @ B[.,512]^T (+bias)
// MODE 0: qkv epilogue -> q/k split-bf16, v split-fp16, q scaled
// MODE 1: proj epilogue -> fp32 out
// =====================================================================
template <int MODE>
__global__ void __launch_bounds__(256, 2) gemm_mma_kernel(
    const __nv_bfloat16* __restrict__ Ahi, const __nv_bfloat16* __restrict__ Alo,
    const __nv_bfloat16* __restrict__ Bhi, const __nv_bfloat16* __restrict__ Blo,
    const float* __restrict__ bias, float* __restrict__ out)
{
    __shared__ __align__(16) __nv_bfloat16 sA[2][128 * 40];
    __shared__ __align__(16) __nv_bfloat16 sB[2][128 * 40];
    int tid = threadIdx.x, lane = tid & 31, wid = tid >> 5;
    int wm = wid >> 1, wn = wid & 1;
    int m0 = blockIdx.y * 128, n0 = blockIdx.x * 128;
    int qr = lane >> 2, qc2 = (lane & 3) * 2;

    float acc[16][4];
#pragma unroll
    for (int i = 0; i < 16; i++)
#pragma unroll
        for (int j = 0; j < 4; j++) acc[i][j] = 0.f;

    int r = tid >> 1, cb = (tid & 1) * 16;
    int arow = imin(m0 + r, MROWS - 1);
    int brow = n0 + r;
    const uint4* gA0 = (const uint4*)(Ahi + (size_t)arow * CDIM);
    const uint4* gA1 = (const uint4*)(Alo + (size_t)arow * CDIM);
    const uint4* gB0 = (const uint4*)(Bhi + (size_t)brow * CDIM);
    const uint4* gB1 = (const uint4*)(Blo + (size_t)brow * CDIM);
    uint32_t sAb = smem_u32(sA);
    uint32_t sBb = smem_u32(sB);

    for (int k0 = 0; k0 < CDIM; k0 += 32) {
        int kq = (k0 + cb) >> 3;
        uint4 va0 = gA0[kq], va0b = gA0[kq + 1];
        uint4 va1 = gA1[kq], va1b = gA1[kq + 1];
        uint4 vb0 = gB0[kq], vb0b = gB0[kq + 1];
        uint4 vb1 = gB1[kq], vb1b = gB1[kq + 1];
        if (k0) __syncthreads();
        *(uint4*)(&sA[0][r * 40 + cb]) = va0;
        *(uint4*)(&sA[0][r * 40 + cb + 8]) = va0b;
        *(uint4*)(&sA[1][r * 40 + cb]) = va1;
        *(uint4*)(&sA[1][r * 40 + cb + 8]) = va1b;
        *(uint4*)(&sB[0][r * 40 + cb]) = vb0;
        *(uint4*)(&sB[0][r * 40 + cb + 8]) = vb0b;
        *(uint4*)(&sB[1][r * 40 + cb]) = vb1;
        *(uint4*)(&sB[1][r * 40 + cb + 8]) = vb1b;
        __syncthreads();

#pragma unroll
        for (int kc = 0; kc < 2; kc++) {
            uint32_t ah[2][4], al[2][4];
#pragma unroll
            for (int mb = 0; mb < 2; mb++) {
                uint32_t ad = sAb +
                    ((wm * 32 + mb * 16 + (lane & 15)) * 40 + kc * 16 + (lane >> 4) * 8) * 2;
                LDSM4(ah[mb][0], ah[mb][1], ah[mb][2], ah[mb][3], ad);
                LDSM4(al[mb][0], al[mb][1], al[mb][2], al[mb][3], ad + 10240);
            }
#pragma unroll
            for (int jp = 0; jp < 4; jp++) {
                uint32_t bd = sBb +
                    ((wn * 64 + jp * 16 + (lane & 7) + ((lane >> 3) & 1) * 8) * 40 +
                     kc * 16 + (lane >> 4) * 8) * 2;
                uint32_t bh[4], bl[4];
                LDSM4(bh[0], bh[1], bh[2], bh[3], bd);
                LDSM4(bl[0], bl[1], bl[2], bl[3], bd + 10240);
#pragma unroll
                for (int mb = 0; mb < 2; mb++) {
                    float* c0 = acc[mb * 8 + jp * 2];
                    float* c1 = acc[mb * 8 + jp * 2 + 1];
                    mma16816(c0, ah[mb], bh[0], bh[2]);
                    mma16816(c0, al[mb], bh[0], bh[2]);
                    mma16816(c0, ah[mb], bl[0], bl[2]);
                    mma16816(c1, ah[mb], bh[1], bh[3]);
                    mma16816(c1, al[mb], bh[1], bh[3]);
                    mma16816(c1, ah[mb], bl[1], bl[3]);
                }
            }
        }
    }

    // ---------------- epilogue ----------------
#pragma unroll
    for (int mb = 0; mb < 2; mb++) {
        int gm0 = m0 + wm * 32 + mb * 16 + qr;
#pragma unroll
        for (int half = 0; half < 2; half++) {
            int gm = gm0 + half * 8;
            if (gm >= MROWS) continue;
            int bb = gm / NTOK;
            int nn = gm - bb * NTOK;
#pragma unroll
            for (int j = 0; j < 8; j++) {
                int col = n0 + wn * 64 + j * 8 + qc2;
                float v0 = acc[mb * 8 + j][half * 2 + 0];
                float v1 = acc[mb * 8 + j][half * 2 + 1];
                float2 bv = *(const float2*)(bias + col);
                v0 += bv.x;
                v1 += bv.y;
                if (MODE == 0) {
                    int s = col >> 9, hh = (col >> 5) & 15, d = col & 31;
                    size_t idx = ((size_t)((bb * NH + hh) * NTOK + nn)) * HD + d;
                    if (s == 0) {
                        uint32_t hi, lo;
                        split_pack2(v0 * QK_SCALE, v1 * QK_SCALE, hi, lo);
                        *(uint32_t*)(g_q_hi + idx) = hi;
                        *(uint32_t*)(g_q_lo + idx) = lo;
                    } else if (s == 1) {
                        uint32_t hi, lo;
                        split_pack2(v0, v1, hi, lo);
                        *(uint32_t*)(g_k_hi + idx) = hi;
                        *(uint32_t*)(g_k_lo + idx) = lo;
                    } else {
                        uint32_t hi, lo;
                        split_pack2h(v0, v1, hi, lo);
                        *(uint32_t*)(g_v_hi + idx) = hi;
                        *(uint32_t*)(g_v_lo + idx) = lo;
                    }
                } else {
                    float2 o = make_float2(v0, v1);
                    *(float2*)(out + (size_t)gm * CDIM + col) = o;
                }
            }
        }
    }
}

// =====================================================================
// HMMA flash attention: q-tile 128 x key-tile 128, hd=32
// QK: bf16 3-term split; PV: P plain fp16, V fp16 2-term split
// =====================================================================
#define ATT_SMEM_BYTES (3 * 2 * 128 * 40 * 2)   // Q,K,V x (hi,lo) x 128x40 x 2B = 61440

__global__ void __launch_bounds__(256, 2) attn_mma_kernel()
{
    extern __shared__ __align__(16) char smc[];
    __nv_bfloat16* sQ = (__nv_bfloat16*)smc;       // hi +0, lo +5120 elems
    __nv_bfloat16* sK = (__nv_bfloat16*)smc + 10240;
    __half* sV = (__half*)smc + 20480;             // hi +0, lo +5120 elems
    uint32_t sQb = smem_u32(sQ);
    uint32_t sKb = smem_u32(sK);
    uint32_t sVb = smem_u32(sV);

    int b = blockIdx.z, h = blockIdx.y, q0 = blockIdx.x * 128;
    int tid = threadIdx.x, lane = tid & 31, wid = tid >> 5;
    int qr = lane >> 2, qc2 = (lane & 3) * 2;
    size_t ho = (size_t)((b * NH + h) * NTOK) * HD;

    // load Q tile (hi+lo), rows clamped
    {
        int r = tid >> 1, cb = (tid & 1) * 16, ci = cb >> 3;
        int gr = imin(q0 + r, NTOK - 1);
        const uint4* s0 = (const uint4*)(g_q_hi + ho + (size_t)gr * HD);
        const uint4* s1 = (const uint4*)(g_q_lo + ho + (size_t)gr * HD);
        *(uint4*)(sQ + r * 40 + cb) = s0[ci];
        *(uint4*)(sQ + r * 40 + cb + 8) = s0[ci + 1];
        *(uint4*)(sQ + 5120 + r * 40 + cb) = s1[ci];
        *(uint4*)(sQ + 5120 + r * 40 + cb + 8) = s1[ci + 1];
    }
    __syncthreads();

    // Q fragments, kept in registers for all 6 key tiles
    uint32_t qh[2][4], ql[2][4];
#pragma unroll
    for (int kc = 0; kc < 2; kc++) {
        uint32_t ad = sQb + ((wid * 16 + (lane & 15)) * 40 + kc * 16 + (lane >> 4) * 8) * 2;
        LDSM4(qh[kc][0], qh[kc][1], qh[kc][2], qh[kc][3], ad);
        LDSM4(ql[kc][0], ql[kc][1], ql[kc][2], ql[kc][3], ad + 10240);
    }

    float O[4][4];
#pragma unroll
    for (int i = 0; i < 4; i++)
#pragma unroll
        for (int j = 0; j < 4; j++) O[i][j] = 0.f;
    float mrow0 = -1e30f, mrow1 = -1e30f, lrow0 = 0.f, lrow1 = 0.f;

    int row0 = q0 + wid * 16 + qr;           // global q row (within batch-head)
    const __nv_bfloat16* bias0 =
        g_biasb + ((size_t)h * NTOK + imin(row0, NTOK - 1)) * NTOK;
    const __nv_bfloat16* bias1 =
        g_biasb + ((size_t)h * NTOK + imin(row0 + 8, NTOK - 1)) * NTOK;

    for (int kt = 0; kt < 6; kt++) {
        int k0 = kt * 128;
        if (kt) __syncthreads();
        // load K (bf16 hi/lo), V (fp16 hi/lo)
        {
            int r = tid >> 1, cb = (tid & 1) * 16, ci = cb >> 3;
            int gr = imin(k0 + r, NTOK - 1);
            const uint4* kh = (const uint4*)(g_k_hi + ho + (size_t)gr * HD);
            const uint4* kl = (const uint4*)(g_k_lo + ho + (size_t)gr * HD);
            const uint4* vh = (const uint4*)(g_v_hi + ho + (size_t)gr * HD);
            const uint4* vl = (const uint4*)(g_v_lo + ho + (size_t)gr * HD);
            *(uint4*)(sK + r * 40 + cb) = kh[ci];
            *(uint4*)(sK + r * 40 + cb + 8) = kh[ci + 1];
            *(uint4*)(sK + 5120 + r * 40 + cb) = kl[ci];
            *(uint4*)(sK + 5120 + r * 40 + cb + 8) = kl[ci + 1];
            *(uint4*)(sV + r * 40 + cb) = vh[ci];
            *(uint4*)(sV + r * 40 + cb + 8) = vh[ci + 1];
            *(uint4*)(sV + 5120 + r * 40 + cb) = vl[ci];
            *(uint4*)(sV + 5120 + r * 40 + cb + 8) = vl[ci + 1];
        }
        __syncthreads();

        // ---- S = Q K^T (3-term bf16 split) ----
        float S[16][4];
#pragma unroll
        for (int i = 0; i < 16; i++)
#pragma unroll
            for (int j = 0; j < 4; j++) S[i][j] = 0.f;

#pragma unroll
        for (int kc = 0; kc < 2; kc++) {
#pragma unroll
            for (int jp = 0; jp < 8; jp++) {
                uint32_t bd = sKb +
                    ((jp * 16 + (lane & 7) + ((lane >> 3) & 1) * 8) * 40 +
                     kc * 16 + (lane >> 4) * 8) * 2;
                uint32_t bh[4], bl[4];
                LDSM4(bh[0], bh[1], bh[2], bh[3], bd);
                LDSM4(bl[0], bl[1], bl[2], bl[3], bd + 10240);
                float* c0 = S[jp * 2];
                float* c1 = S[jp * 2 + 1];
                mma16816(c0, qh[kc], bh[0], bh[2]);
                mma16816(c0, ql[kc], bh[0], bh[2]);
                mma16816(c0, qh[kc], bl[0], bl[2]);
                mma16816(c1, qh[kc], bh[1], bh[3]);
                mma16816(c1, ql[kc], bh[1], bh[3]);
                mma16816(c1, qh[kc], bl[1], bl[3]);
            }
        }

        // ---- bias (bf16) + key mask ----
        int kv = NTOK - k0;
#pragma unroll
        for (int j = 0; j < 16; j++) {
            int c = j * 8 + qc2;
            float2 b0 = __bfloat1622float2(
                *(const __nv_bfloat162*)(bias0 + k0 + c));
            float2 b1 = __bfloat1622float2(
                *(const __nv_bfloat162*)(bias1 + k0 + c));
            S[j][0] += b0.x; S[j][1] += b0.y;
            S[j][2] += b1.x; S[j][3] += b1.y;
            if (c >= kv)     { S[j][0] = -1e30f; S[j][2] = -1e30f; }
            if (c + 1 >= kv) { S[j][1] = -1e30f; S[j][3] = -1e30f; }
        }

        // ---- online softmax ----
        float m0l = -1e30f, m1l = -1e30f;
#pragma unroll
        for (int j = 0; j < 16; j++) {
            m0l = fmaxf(m0l, fmaxf(S[j][0], S[j][1]));
            m1l = fmaxf(m1l, fmaxf(S[j][2], S[j][3]));
        }
        m0l = fmaxf(m0l, __shfl_xor_sync(0xffffffffu, m0l, 1));
        m0l = fmaxf(m0l, __shfl_xor_sync(0xffffffffu, m0l, 2));
        m1l = fmaxf(m1l, __shfl_xor_sync(0xffffffffu, m1l, 1));
        m1l = fmaxf(m1l, __shfl_xor_sync(0xffffffffu, m1l, 2));
        float mn0 = fmaxf(mrow0, m0l), mn1 = fmaxf(mrow1, m1l);
        float corr0 = __expf(mrow0 - mn0), corr1 = __expf(mrow1 - mn1);
        mrow0 = mn0; mrow1 = mn1;
        float s0 = 0.f, s1 = 0.f;
#pragma unroll
        for (int j = 0; j < 16; j++) {
            S[j][0] = __expf(S[j][0] - mn0); s0 += S[j][0];
            S[j][1] = __expf(S[j][1] - mn0); s0 += S[j][1];
            S[j][2] = __expf(S[j][2] - mn1); s1 += S[j][2];
            S[j][3] = __expf(S[j][3] - mn1); s1 += S[j][3];
        }
        s0 += __shfl_xor_sync(0xffffffffu, s0, 1);
        s0 += __shfl_xor_sync(0xffffffffu, s0, 2);
        s1 += __shfl_xor_sync(0xffffffffu, s1, 1);
        s1 += __shfl_xor_sync(0xffffffffu, s1, 2);
        lrow0 = lrow0 * corr0 + s0;
        lrow1 = lrow1 * corr1 + s1;
#pragma unroll
        for (int jd = 0; jd < 4; jd++) {
            O[jd][0] *= corr0; O[jd][1] *= corr0;
            O[jd][2] *= corr1; O[jd][3] *= corr1;
        }

        // ---- O += P V : P plain fp16, V fp16 2-term split ----
#pragma unroll
        for (int kc = 0; kc < 8; kc++) {
            uint32_t pa[4];
            pa[0] = pack_h2(S[2 * kc][0], S[2 * kc][1]);
            pa[1] = pack_h2(S[2 * kc][2], S[2 * kc][3]);
            pa[2] = pack_h2(S[2 * kc + 1][0], S[2 * kc + 1][1]);
            pa[3] = pack_h2(S[2 * kc + 1][2], S[2 * kc + 1][3]);
            uint32_t vrow = kc * 16 + (lane & 7) + ((lane >> 3) & 1) * 8;
            uint32_t vcb = (lane >> 4) * 8;
            uint32_t vd0 = sVb + (vrow * 40 + vcb) * 2;
            uint32_t vd1 = sVb + (vrow * 40 + 16 + vcb) * 2;
            uint32_t vh[8], vl[8];
            LDSM4T(vh[0], vh[1], vh[2], vh[3], vd0);
            LDSM4T(vh[4], vh[5], vh[6], vh[7], vd1);
            LDSM4T(vl[0], vl[1], vl[2], vl[3], vd0 + 10240);
            LDSM4T(vl[4], vl[5], vl[6], vl[7], vd1 + 10240);
            mma16816h(O[0], pa, vh[0], vh[1]);
            mma16816h(O[0], pa, vl[0], vl[1]);
            mma16816h(O[1], pa, vh[2], vh[3]);
            mma16816h(O[1], pa, vl[2], vl[3]);
            mma16816h(O[2], pa, vh[4], vh[5]);
            mma16816h(O[2], pa, vl[4], vl[5]);
            mma16816h(O[3], pa, vh[6], vh[7]);
            mma16816h(O[3], pa, vl[6], vl[7]);
        }
    }

    // ---- output: normalize, split to bf16 hi/lo for proj GEMM ----
    float li0 = 1.f / lrow0, li1 = 1.f / lrow1;
#pragma unroll
    for (int jd = 0; jd < 4; jd++) {
        int d = jd * 8 + qc2;
        if (row0 < NTOK) {
            uint32_t hi, lo;
            split_pack2(O[jd][0] * li0, O[jd][1] * li0, hi, lo);
            size_t idx = ((size_t)(b * NTOK + row0)) * CDIM + h * HD + d;
            *(uint32_t*)(g_Ahi + idx) = hi;
            *(uint32_t*)(g_Alo + idx) = lo;
        }
        if (row0 + 8 < NTOK) {
            uint32_t hi, lo;
            split_pack2(O[jd][2] * li1, O[jd][3] * li1, hi, lo);
            size_t idx = ((size_t)(b * NTOK + row0 + 8)) * CDIM + h * HD + d;
            *(uint32_t*)(g_Ahi + idx) = hi;
            *(uint32_t*)(g_Alo + idx) = lo;
        }
    }
}

// =====================================================================
extern "C" void kernel_launch(void* const* d_in, const int* in_sizes, int n_in,
                              void* d_out, int out_size)
{
    const float* x    = (const float*)d_in[0];
    const float* Wqkv = (const float*)d_in[1];
    const float* bqkv = (const float*)d_in[2];
    const float* Wprj = (const float*)d_in[3];
    const float* bprj = (const float*)d_in[4];
    const float* btt  = (const float*)d_in[5];
    const float* btm  = (const float*)d_in[6];
    const float* ttt  = (const float*)d_in[7];
    const float* tgt  = (const float*)d_in[8];
    const float* ttl  = (const float*)d_in[9];
    const float* tgl  = (const float*)d_in[10];
    float* out = (float*)d_out;

    cudaFuncSetAttribute(attn_mma_kernel, cudaFuncAttributeMaxDynamicSharedMemorySize,
                         ATT_SMEM_BYTES);

    __nv_bfloat16 *pAhi, *pAlo, *pWhi, *pWlo, *pPhi, *pPlo;
    cudaGetSymbolAddress((void**)&pAhi, g_Ahi);
    cudaGetSymbolAddress((void**)&pAlo, g_Alo);
    cudaGetSymbolAddress((void**)&pWhi, g_Whi);
    cudaGetSymbolAddress((void**)&pWlo, g_Wlo);
    cudaGetSymbolAddress((void**)&pPhi, g_Phi);
    cudaGetSymbolAddress((void**)&pPlo, g_Plo);

    const int n4 = MROWS * CDIM / 4;

    build_bias_kernel<<<dim3((NTOK * NTOK + 255) / 256, NH), 256>>>(
        btt, btm, ttt, tgt, ttl, tgl);
    split_kernel<<<(n4 + 255) / 256, 256>>>(x, pAhi, pAlo, n4);
    tsplit_kernel<<<dim3(1536 / 32, 512 / 32), dim3(32, 8)>>>(Wqkv, pWhi, pWlo, 512, 1536);
    tsplit_kernel<<<dim3(512 / 32, 512 / 32), dim3(32, 8)>>>(Wprj, pPhi, pPlo, 512, 512);
    gemm_mma_kernel<0><<<dim3(12, 93), 256>>>(pAhi, pAlo, pWhi, pWlo, bqkv, nullptr);
    attn_mma_kernel<<<dim3(6, NH, NB), 256, ATT_SMEM_BYTES>>>();
    gemm_mma_kernel<1><<<dim3(4, 93), 256>>>(pAhi, pAlo, pPhi, pPlo, bprj, out);
}

// round 15
// speedup vs baseline: 2.1083x; 1.0565x over previous
#include <cuda_runtime.h>
#include <cuda_bf16.h>
#include <cuda_fp16.h>
#include <cstdint>
#include <math.h>

#define NB 16
#define NH 16
#define NTOK 740
#define HD 32
#define CDIM 512
#define MROWS (NB * NTOK)            // 11840
#define BHND (NB * NH * NTOK * HD)   // 6062080
#define QK_SCALE 0.17677669529663687f

// ---------------- device scratch ----------------
__device__ __align__(16) __nv_bfloat16 g_biasb[NH * NTOK * NTOK + 256];
__device__ __align__(16) __nv_bfloat16 g_Ahi[MROWS * CDIM];   // x split (qkv A side)
__device__ __align__(16) __nv_bfloat16 g_Alo[MROWS * CDIM];
__device__ __align__(16) __half       g_A16[MROWS * CDIM];    // attn out (proj A side)
__device__ __align__(16) __nv_bfloat16 g_Whi[3 * CDIM * CDIM]; // W_qkv^T [1536,512]
__device__ __align__(16) __nv_bfloat16 g_Wlo[3 * CDIM * CDIM];
__device__ __align__(16) __half g_Phi[CDIM * CDIM];            // W_proj^T fp16 hi
__device__ __align__(16) __half g_Plo[CDIM * CDIM];            // W_proj^T fp16 lo
__device__ __align__(16) __nv_bfloat16 g_q_hi[BHND];
__device__ __align__(16) __nv_bfloat16 g_q_lo[BHND];
__device__ __align__(16) __nv_bfloat16 g_k_hi[BHND];
__device__ __align__(16) __nv_bfloat16 g_k_lo[BHND];
__device__ __align__(16) __half g_v16[BHND];                   // V single fp16

// ================= helpers (base-ISA only: mma.sync / ldmatrix) =================
__device__ __forceinline__ uint32_t smem_u32(const void* p) {
    uint32_t a;
    asm("{ .reg .u64 t; cvta.to.shared.u64 t, %1; cvt.u32.u64 %0, t; }" : "=r"(a) : "l"(p));
    return a;
}

__device__ __forceinline__ void mma16816(float c[4], const uint32_t a[4],
                                         uint32_t b0, uint32_t b1) {
    asm volatile(
        "mma.sync.aligned.m16n8k16.row.col.f32.bf16.bf16.f32 "
        "{%0,%1,%2,%3}, {%4,%5,%6,%7}, {%8,%9}, {%0,%1,%2,%3};"
        : "+f"(c[0]), "+f"(c[1]), "+f"(c[2]), "+f"(c[3])
        : "r"(a[0]), "r"(a[1]), "r"(a[2]), "r"(a[3]), "r"(b0), "r"(b1));
}

__device__ __forceinline__ void mma16816h(float c[4], const uint32_t a[4],
                                          uint32_t b0, uint32_t b1) {
    asm volatile(
        "mma.sync.aligned.m16n8k16.row.col.f32.f16.f16.f32 "
        "{%0,%1,%2,%3}, {%4,%5,%6,%7}, {%8,%9}, {%0,%1,%2,%3};"
        : "+f"(c[0]), "+f"(c[1]), "+f"(c[2]), "+f"(c[3])
        : "r"(a[0]), "r"(a[1]), "r"(a[2]), "r"(a[3]), "r"(b0), "r"(b1));
}

#define LDSM4(R0, R1, R2, R3, ADDR) \
    asm volatile("ldmatrix.sync.aligned.m8n8.x4.shared.b16 {%0,%1,%2,%3}, [%4];" \
        : "=r"(R0), "=r"(R1), "=r"(R2), "=r"(R3) : "r"(ADDR))

#define LDSM4T(R0, R1, R2, R3, ADDR) \
    asm volatile("ldmatrix.sync.aligned.m8n8.x4.trans.shared.b16 {%0,%1,%2,%3}, [%4];" \
        : "=r"(R0), "=r"(R1), "=r"(R2), "=r"(R3) : "r"(ADDR))

// split fp32 pair -> packed bf16 hi pair + lo (residual) pair
__device__ __forceinline__ void split_pack2(float f0, float f1,
                                            uint32_t& hi, uint32_t& lo) {
    __nv_bfloat16 h0 = __float2bfloat16(f0);
    __nv_bfloat16 h1 = __float2bfloat16(f1);
    __nv_bfloat162 hv(h0, h1);
    hi = *reinterpret_cast<uint32_t*>(&hv);
    __nv_bfloat162 lv(__float2bfloat16(f0 - __bfloat162float(h0)),
                      __float2bfloat16(f1 - __bfloat162float(h1)));
    lo = *reinterpret_cast<uint32_t*>(&lv);
}

__device__ __forceinline__ uint32_t pack_h2(float f0, float f1) {
    __half2 h = __floats2half2_rn(f0, f1);
    return *reinterpret_cast<uint32_t*>(&h);
}

__device__ __forceinline__ int imin(int a, int b) { return a < b ? a : b; }

// =====================================================================
// Bias assembly (bf16 output)
// =====================================================================
__global__ void build_bias_kernel(const float* __restrict__ btt,
                                  const float* __restrict__ btm,
                                  const float* __restrict__ ttt,
                                  const float* __restrict__ tgt,
                                  const float* __restrict__ ttl,
                                  const float* __restrict__ tgl)
{
    int p = blockIdx.x * 256 + threadIdx.x;
    if (p >= NTOK * NTOK) return;
    int h = blockIdx.y;
    int i = p / NTOK, j = p - i * NTOK;
    float v;
    if (i < 256) {
        if (j < 256) {
            int ai = i >> 4, bi = i & 15, aj = j >> 4, bj = j & 15;
            int idx = (ai - aj + 15) * 31 + (bi - bj + 15);
            v = btm[idx * NH + h];
        } else {
            v = tgt[h * 256 + i] + tgl[h * 484 + (j - 256)];
        }
    } else {
        int i2 = i - 256;
        if (j < 256) {
            v = ttt[h * 484 + i2] + ttl[h * 256 + j];
        } else {
            int j2 = j - 256;
            int ai = i2 / 22, bi = i2 - ai * 22;
            int aj = j2 / 22, bj = j2 - aj * 22;
            int idx = (ai - aj + 21) * 43 + (bi - bj + 21);
            v = btt[idx * NH + h];
        }
    }
    g_biasb[h * NTOK * NTOK + p] = __float2bfloat16(v);
}

// =====================================================================
// fp32 -> (hi, lo) bf16 split, elementwise
// =====================================================================
__global__ void split_kernel(const float* __restrict__ in,
                             __nv_bfloat16* __restrict__ hi,
                             __nv_bfloat16* __restrict__ lo, int n4)
{
    int i = blockIdx.x * 256 + threadIdx.x;
    if (i >= n4) return;
    float4 v = ((const float4*)in)[i];
    uint32_t h0, l0, h1, l1;
    split_pack2(v.x, v.y, h0, l0);
    split_pack2(v.z, v.w, h1, l1);
    uint2* ph = (uint2*)hi;
    uint2* pl = (uint2*)lo;
    ph[i] = make_uint2(h0, h1);
    pl[i] = make_uint2(l0, l1);
}

// =====================================================================
// Transpose + split: W[K,NN] fp32 -> hi/lo[NN,K] bf16
// =====================================================================
__global__ void tsplit_kernel(const float* __restrict__ W,
                              __nv_bfloat16* __restrict__ hi,
                              __nv_bfloat16* __restrict__ lo, int K, int NN)
{
    __shared__ float t[32][33];
    int nb = blockIdx.x * 32, kb = blockIdx.y * 32;
    int tx = threadIdx.x, ty = threadIdx.y;
#pragma unroll
    for (int i = 0; i < 32; i += 8)
        t[ty + i][tx] = W[(size_t)(kb + ty + i) * NN + nb + tx];
    __syncthreads();
#pragma unroll
    for (int i = 0; i < 32; i += 8) {
        float v = t[tx][ty + i];
        __nv_bfloat16 h = __float2bfloat16(v);
        __nv_bfloat16 l = __float2bfloat16(v - __bfloat162float(h));
        size_t o = (size_t)(nb + ty + i) * K + kb + tx;
        hi[o] = h;
        lo[o] = l;
    }
}

// =====================================================================
// Transpose + split: W[K,NN] fp32 -> hi/lo[NN,K] fp16 (for proj)
// =====================================================================
__global__ void tsplit_h_kernel(const float* __restrict__ W,
                                __half* __restrict__ hi,
                                __half* __restrict__ lo, int K, int NN)
{
    __shared__ float t[32][33];
    int nb = blockIdx.x * 32, kb = blockIdx.y * 32;
    int tx = threadIdx.x, ty = threadIdx.y;
#pragma unroll
    for (int i = 0; i < 32; i += 8)
        t[ty + i][tx] = W[(size_t)(kb + ty + i) * NN + nb + tx];
    __syncthreads();
#pragma unroll
    for (int i = 0; i < 32; i += 8) {
        float v = t[tx][ty + i];
        __half h = __float2half_rn(v);
        __half l = __float2half_rn(v - __half2float(h));
        size_t o = (size_t)(nb + ty + i) * K + kb + tx;
        hi[o] = h;
        lo[o] = l;
    }
}

// =====================================================================
// HMMA split-bf16 GEMM (qkv): C = x @ W_qkv^T (+bias)
// epilogue -> q/k split-bf16 (q scaled), v single fp16
// =====================================================================
__global__ void __launch_bounds__(256, 2) gemm_qkv_kernel(
    const __nv_bfloat16* __restrict__ Ahi, const __nv_bfloat16* __restrict__ Alo,
    const __nv_bfloat16* __restrict__ Bhi, const __nv_bfloat16* __restrict__ Blo,
    const float* __restrict__ bias)
{
    __shared__ __align__(16) __nv_bfloat16 sA[2][128 * 40];
    __shared__ __align__(16) __nv_bfloat16 sB[2][128 * 40];
    int tid = threadIdx.x, lane = tid & 31, wid = tid >> 5;
    int wm = wid >> 1, wn = wid & 1;
    int m0 = blockIdx.y * 128, n0 = blockIdx.x * 128;
    int qr = lane >> 2, qc2 = (lane & 3) * 2;

    float acc[16][4];
#pragma unroll
    for (int i = 0; i < 16; i++)
#pragma unroll
        for (int j = 0; j < 4; j++) acc[i][j] = 0.f;

    int r = tid >> 1, cb = (tid & 1) * 16;
    int arow = imin(m0 + r, MROWS - 1);
    int brow = n0 + r;
    const uint4* gA0 = (const uint4*)(Ahi + (size_t)arow * CDIM);
    const uint4* gA1 = (const uint4*)(Alo + (size_t)arow * CDIM);
    const uint4* gB0 = (const uint4*)(Bhi + (size_t)brow * CDIM);
    const uint4* gB1 = (const uint4*)(Blo + (size_t)brow * CDIM);
    uint32_t sAb = smem_u32(sA);
    uint32_t sBb = smem_u32(sB);

    for (int k0 = 0; k0 < CDIM; k0 += 32) {
        int kq = (k0 + cb) >> 3;
        uint4 va0 = gA0[kq], va0b = gA0[kq + 1];
        uint4 va1 = gA1[kq], va1b = gA1[kq + 1];
        uint4 vb0 = gB0[kq], vb0b = gB0[kq + 1];
        uint4 vb1 = gB1[kq], vb1b = gB1[kq + 1];
        if (k0) __syncthreads();
        *(uint4*)(&sA[0][r * 40 + cb]) = va0;
        *(uint4*)(&sA[0][r * 40 + cb + 8]) = va0b;
        *(uint4*)(&sA[1][r * 40 + cb]) = va1;
        *(uint4*)(&sA[1][r * 40 + cb + 8]) = va1b;
        *(uint4*)(&sB[0][r * 40 + cb]) = vb0;
        *(uint4*)(&sB[0][r * 40 + cb + 8]) = vb0b;
        *(uint4*)(&sB[1][r * 40 + cb]) = vb1;
        *(uint4*)(&sB[1][r * 40 + cb + 8]) = vb1b;
        __syncthreads();

#pragma unroll
        for (int kc = 0; kc < 2; kc++) {
            uint32_t ah[2][4], al[2][4];
#pragma unroll
            for (int mb = 0; mb < 2; mb++) {
                uint32_t ad = sAb +
                    ((wm * 32 + mb * 16 + (lane & 15)) * 40 + kc * 16 + (lane >> 4) * 8) * 2;
                LDSM4(ah[mb][0], ah[mb][1], ah[mb][2], ah[mb][3], ad);
                LDSM4(al[mb][0], al[mb][1], al[mb][2], al[mb][3], ad + 10240);
            }
#pragma unroll
            for (int jp = 0; jp < 4; jp++) {
                uint32_t bd = sBb +
                    ((wn * 64 + jp * 16 + (lane & 7) + ((lane >> 3) & 1) * 8) * 40 +
                     kc * 16 + (lane >> 4) * 8) * 2;
                uint32_t bh[4], bl[4];
                LDSM4(bh[0], bh[1], bh[2], bh[3], bd);
                LDSM4(bl[0], bl[1], bl[2], bl[3], bd + 10240);
#pragma unroll
                for (int mb = 0; mb < 2; mb++) {
                    float* c0 = acc[mb * 8 + jp * 2];
                    float* c1 = acc[mb * 8 + jp * 2 + 1];
                    mma16816(c0, ah[mb], bh[0], bh[2]);
                    mma16816(c0, al[mb], bh[0], bh[2]);
                    mma16816(c0, ah[mb], bl[0], bl[2]);
                    mma16816(c1, ah[mb], bh[1], bh[3]);
                    mma16816(c1, al[mb], bh[1], bh[3]);
                    mma16816(c1, ah[mb], bl[1], bl[3]);
                }
            }
        }
    }

    // ---------------- epilogue ----------------
#pragma unroll
    for (int mb = 0; mb < 2; mb++) {
        int gm0 = m0 + wm * 32 + mb * 16 + qr;
#pragma unroll
        for (int half = 0; half < 2; half++) {
            int gm = gm0 + half * 8;
            if (gm >= MROWS) continue;
            int bb = gm / NTOK;
            int nn = gm - bb * NTOK;
#pragma unroll
            for (int j = 0; j < 8; j++) {
                int col = n0 + wn * 64 + j * 8 + qc2;
                float v0 = acc[mb * 8 + j][half * 2 + 0];
                float v1 = acc[mb * 8 + j][half * 2 + 1];
                float2 bv = *(const float2*)(bias + col);
                v0 += bv.x;
                v1 += bv.y;
                int s = col >> 9, hh = (col >> 5) & 15, d = col & 31;
                size_t idx = ((size_t)((bb * NH + hh) * NTOK + nn)) * HD + d;
                if (s == 0) {
                    uint32_t hi, lo;
                    split_pack2(v0 * QK_SCALE, v1 * QK_SCALE, hi, lo);
                    *(uint32_t*)(g_q_hi + idx) = hi;
                    *(uint32_t*)(g_q_lo + idx) = lo;
                } else if (s == 1) {
                    uint32_t hi, lo;
                    split_pack2(v0, v1, hi, lo);
                    *(uint32_t*)(g_k_hi + idx) = hi;
                    *(uint32_t*)(g_k_lo + idx) = lo;
                } else {
                    *(uint32_t*)(g_v16 + idx) = pack_h2(v0, v1);
                }
            }
        }
    }
}

// =====================================================================
// HMMA proj GEMM: out = A16 @ (Phi+Plo)^T + bias  (A fp16 single, W fp16 2-term)
// =====================================================================
__global__ void __launch_bounds__(256, 2) gemm_proj_kernel(
    const __half* __restrict__ A16,
    const __half* __restrict__ Bhi, const __half* __restrict__ Blo,
    const float* __restrict__ bias, float* __restrict__ out)
{
    __shared__ __align__(16) __half sA[128 * 40];
    __shared__ __align__(16) __half sB[2][128 * 40];
    int tid = threadIdx.x, lane = tid & 31, wid = tid >> 5;
    int wm = wid >> 1, wn = wid & 1;
    int m0 = blockIdx.y * 128, n0 = blockIdx.x * 128;
    int qr = lane >> 2, qc2 = (lane & 3) * 2;

    float acc[16][4];
#pragma unroll
    for (int i = 0; i < 16; i++)
#pragma unroll
        for (int j = 0; j < 4; j++) acc[i][j] = 0.f;

    int r = tid >> 1, cb = (tid & 1) * 16;
    int arow = imin(m0 + r, MROWS - 1);
    int brow = n0 + r;
    const uint4* gA0 = (const uint4*)(A16 + (size_t)arow * CDIM);
    const uint4* gB0 = (const uint4*)(Bhi + (size_t)brow * CDIM);
    const uint4* gB1 = (const uint4*)(Blo + (size_t)brow * CDIM);
    uint32_t sAb = smem_u32(sA);
    uint32_t sBb = smem_u32(sB);

    for (int k0 = 0; k0 < CDIM; k0 += 32) {
        int kq = (k0 + cb) >> 3;
        uint4 va0 = gA0[kq], va0b = gA0[kq + 1];
        uint4 vb0 = gB0[kq], vb0b = gB0[kq + 1];
        uint4 vb1 = gB1[kq], vb1b = gB1[kq + 1];
        if (k0) __syncthreads();
        *(uint4*)(&sA[r * 40 + cb]) = va0;
        *(uint4*)(&sA[r * 40 + cb + 8]) = va0b;
        *(uint4*)(&sB[0][r * 40 + cb]) = vb0;
        *(uint4*)(&sB[0][r * 40 + cb + 8]) = vb0b;
        *(uint4*)(&sB[1][r * 40 + cb]) = vb1;
        *(uint4*)(&sB[1][r * 40 + cb + 8]) = vb1b;
        __syncthreads();

#pragma unroll
        for (int kc = 0; kc < 2; kc++) {
            uint32_t a16[2][4];
#pragma unroll
            for (int mb = 0; mb < 2; mb++) {
                uint32_t ad = sAb +
                    ((wm * 32 + mb * 16 + (lane & 15)) * 40 + kc * 16 + (lane >> 4) * 8) * 2;
                LDSM4(a16[mb][0], a16[mb][1], a16[mb][2], a16[mb][3], ad);
            }
#pragma unroll
            for (int jp = 0; jp < 4; jp++) {
                uint32_t bd = sBb +
                    ((wn * 64 + jp * 16 + (lane & 7) + ((lane >> 3) & 1) * 8) * 40 +
                     kc * 16 + (lane >> 4) * 8) * 2;
                uint32_t bh[4], bl[4];
                LDSM4(bh[0], bh[1], bh[2], bh[3], bd);
                LDSM4(bl[0], bl[1], bl[2], bl[3], bd + 10240);
#pragma unroll
                for (int mb = 0; mb < 2; mb++) {
                    float* c0 = acc[mb * 8 + jp * 2];
                    float* c1 = acc[mb * 8 + jp * 2 + 1];
                    mma16816h(c0, a16[mb], bh[0], bh[2]);
                    mma16816h(c0, a16[mb], bl[0], bl[2]);
                    mma16816h(c1, a16[mb], bh[1], bh[3]);
                    mma16816h(c1, a16[mb], bl[1], bl[3]);
                }
            }
        }
    }

    // ---------------- epilogue ----------------
#pragma unroll
    for (int mb = 0; mb < 2; mb++) {
        int gm0 = m0 + wm * 32 + mb * 16 + qr;
#pragma unroll
        for (int half = 0; half < 2; half++) {
            int gm = gm0 + half * 8;
            if (gm >= MROWS) continue;
#pragma unroll
            for (int j = 0; j < 8; j++) {
                int col = n0 + wn * 64 + j * 8 + qc2;
                float v0 = acc[mb * 8 + j][half * 2 + 0];
                float v1 = acc[mb * 8 + j][half * 2 + 1];
                float2 bv = *(const float2*)(bias + col);
                float2 o = make_float2(v0 + bv.x, v1 + bv.y);
                *(float2*)(out + (size_t)gm * CDIM + col) = o;
            }
        }
    }
}

// =====================================================================
// HMMA flash attention: q-tile 128 x key-tile 128, hd=32
// QK: bf16 3-term split; PV: P fp16 x V single fp16
// smem: Q(hi,lo) 20480B | K(hi,lo) 20480B | V 10240B = 51200B
// =====================================================================
#define ATT_SMEM_BYTES 51200

__global__ void __launch_bounds__(256, 2) attn_mma_kernel()
{
    extern __shared__ __align__(16) char smc[];
    __nv_bfloat16* sQ = (__nv_bfloat16*)smc;       // hi +0, lo +5120 elems
    __nv_bfloat16* sK = (__nv_bfloat16*)smc + 10240;
    __half* sV = (__half*)smc + 20480;             // single, 5120 elems
    uint32_t sQb = smem_u32(sQ);
    uint32_t sKb = smem_u32(sK);
    uint32_t sVb = smem_u32(sV);

    int b = blockIdx.z, h = blockIdx.y, q0 = blockIdx.x * 128;
    int tid = threadIdx.x, lane = tid & 31, wid = tid >> 5;
    int qr = lane >> 2, qc2 = (lane & 3) * 2;
    size_t ho = (size_t)((b * NH + h) * NTOK) * HD;

    // load Q tile (hi+lo), rows clamped
    {
        int r = tid >> 1, cb = (tid & 1) * 16, ci = cb >> 3;
        int gr = imin(q0 + r, NTOK - 1);
        const uint4* s0 = (const uint4*)(g_q_hi + ho + (size_t)gr * HD);
        const uint4* s1 = (const uint4*)(g_q_lo + ho + (size_t)gr * HD);
        *(uint4*)(sQ + r * 40 + cb) = s0[ci];
        *(uint4*)(sQ + r * 40 + cb + 8) = s0[ci + 1];
        *(uint4*)(sQ + 5120 + r * 40 + cb) = s1[ci];
        *(uint4*)(sQ + 5120 + r * 40 + cb + 8) = s1[ci + 1];
    }
    __syncthreads();

    // Q fragments, kept in registers for all 6 key tiles
    uint32_t qh[2][4], ql[2][4];
#pragma unroll
    for (int kc = 0; kc < 2; kc++) {
        uint32_t ad = sQb + ((wid * 16 + (lane & 15)) * 40 + kc * 16 + (lane >> 4) * 8) * 2;
        LDSM4(qh[kc][0], qh[kc][1], qh[kc][2], qh[kc][3], ad);
        LDSM4(ql[kc][0], ql[kc][1], ql[kc][2], ql[kc][3], ad + 10240);
    }

    float O[4][4];
#pragma unroll
    for (int i = 0; i < 4; i++)
#pragma unroll
        for (int j = 0; j < 4; j++) O[i][j] = 0.f;
    float mrow0 = -1e30f, mrow1 = -1e30f, lrow0 = 0.f, lrow1 = 0.f;

    int row0 = q0 + wid * 16 + qr;           // global q row (within batch-head)
    const __nv_bfloat16* bias0 =
        g_biasb + ((size_t)h * NTOK + imin(row0, NTOK - 1)) * NTOK;
    const __nv_bfloat16* bias1 =
        g_biasb + ((size_t)h * NTOK + imin(row0 + 8, NTOK - 1)) * NTOK;

    for (int kt = 0; kt < 6; kt++) {
        int k0 = kt * 128;
        if (kt) __syncthreads();
        // load K (bf16 hi/lo), V (fp16 single)
        {
            int r = tid >> 1, cb = (tid & 1) * 16, ci = cb >> 3;
            int gr = imin(k0 + r, NTOK - 1);
            const uint4* kh = (const uint4*)(g_k_hi + ho + (size_t)gr * HD);
            const uint4* kl = (const uint4*)(g_k_lo + ho + (size_t)gr * HD);
            const uint4* vh = (const uint4*)(g_v16 + ho + (size_t)gr * HD);
            *(uint4*)(sK + r * 40 + cb) = kh[ci];
            *(uint4*)(sK + r * 40 + cb + 8) = kh[ci + 1];
            *(uint4*)(sK + 5120 + r * 40 + cb) = kl[ci];
            *(uint4*)(sK + 5120 + r * 40 + cb + 8) = kl[ci + 1];
            *(uint4*)(sV + r * 40 + cb) = vh[ci];
            *(uint4*)(sV + r * 40 + cb + 8) = vh[ci + 1];
        }
        __syncthreads();

        // ---- S = Q K^T (3-term bf16 split) ----
        float S[16][4];
#pragma unroll
        for (int i = 0; i < 16; i++)
#pragma unroll
            for (int j = 0; j < 4; j++) S[i][j] = 0.f;

#pragma unroll
        for (int kc = 0; kc < 2; kc++) {
#pragma unroll
            for (int jp = 0; jp < 8; jp++) {
                uint32_t bd = sKb +
                    ((jp * 16 + (lane & 7) + ((lane >> 3) & 1) * 8) * 40 +
                     kc * 16 + (lane >> 4) * 8) * 2;
                uint32_t bh[4], bl[4];
                LDSM4(bh[0], bh[1], bh[2], bh[3], bd);
                LDSM4(bl[0], bl[1], bl[2], bl[3], bd + 10240);
                float* c0 = S[jp * 2];
                float* c1 = S[jp * 2 + 1];
                mma16816(c0, qh[kc], bh[0], bh[2]);
                mma16816(c0, ql[kc], bh[0], bh[2]);
                mma16816(c0, qh[kc], bl[0], bl[2]);
                mma16816(c1, qh[kc], bh[1], bh[3]);
                mma16816(c1, ql[kc], bh[1], bh[3]);
                mma16816(c1, qh[kc], bl[1], bl[3]);
            }
        }

        // ---- bias (bf16) + key mask ----
        int kv = NTOK - k0;
#pragma unroll
        for (int j = 0; j < 16; j++) {
            int c = j * 8 + qc2;
            float2 b0 = __bfloat1622float2(
                *(const __nv_bfloat162*)(bias0 + k0 + c));
            float2 b1 = __bfloat1622float2(
                *(const __nv_bfloat162*)(bias1 + k0 + c));
            S[j][0] += b0.x; S[j][1] += b0.y;
            S[j][2] += b1.x; S[j][3] += b1.y;
            if (c >= kv)     { S[j][0] = -1e30f; S[j][2] = -1e30f; }
            if (c + 1 >= kv) { S[j][1] = -1e30f; S[j][3] = -1e30f; }
        }

        // ---- online softmax ----
        float m0l = -1e30f, m1l = -1e30f;
#pragma unroll
        for (int j = 0; j < 16; j++) {
            m0l = fmaxf(m0l, fmaxf(S[j][0], S[j][1]));
            m1l = fmaxf(m1l, fmaxf(S[j][2], S[j][3]));
        }
        m0l = fmaxf(m0l, __shfl_xor_sync(0xffffffffu, m0l, 1));
        m0l = fmaxf(m0l, __shfl_xor_sync(0xffffffffu, m0l, 2));
        m1l = fmaxf(m1l, __shfl_xor_sync(0xffffffffu, m1l, 1));
        m1l = fmaxf(m1l, __shfl_xor_sync(0xffffffffu, m1l, 2));
        float mn0 = fmaxf(mrow0, m0l), mn1 = fmaxf(mrow1, m1l);
        float corr0 = __expf(mrow0 - mn0), corr1 = __expf(mrow1 - mn1);
        mrow0 = mn0; mrow1 = mn1;
        float s0 = 0.f, s1 = 0.f;
#pragma unroll
        for (int j = 0; j < 16; j++) {
            S[j][0] = __expf(S[j][0] - mn0); s0 += S[j][0];
            S[j][1] = __expf(S[j][1] - mn0); s0 += S[j][1];
            S[j][2] = __expf(S[j][2] - mn1); s1 += S[j][2];
            S[j][3] = __expf(S[j][3] - mn1); s1 += S[j][3];
        }
        s0 += __shfl_xor_sync(0xffffffffu, s0, 1);
        s0 += __shfl_xor_sync(0xffffffffu, s0, 2);
        s1 += __shfl_xor_sync(0xffffffffu, s1, 1);
        s1 += __shfl_xor_sync(0xffffffffu, s1, 2);
        lrow0 = lrow0 * corr0 + s0;
        lrow1 = lrow1 * corr1 + s1;
#pragma unroll
        for (int jd = 0; jd < 4; jd++) {
            O[jd][0] *= corr0; O[jd][1] *= corr0;
            O[jd][2] *= corr1; O[jd][3] *= corr1;
        }

        // ---- O += P V : P fp16, V single fp16 ----
#pragma unroll
        for (int kc = 0; kc < 8; kc++) {
            uint32_t pa[4];
            pa[0] = pack_h2(S[2 * kc][0], S[2 * kc][1]);
            pa[1] = pack_h2(S[2 * kc][2], S[2 * kc][3]);
            pa[2] = pack_h2(S[2 * kc + 1][0], S[2 * kc + 1][1]);
            pa[3] = pack_h2(S[2 * kc + 1][2], S[2 * kc + 1][3]);
            uint32_t vrow = kc * 16 + (lane & 7) + ((lane >> 3) & 1) * 8;
            uint32_t vcb = (lane >> 4) * 8;
            uint32_t vd0 = sVb + (vrow * 40 + vcb) * 2;
            uint32_t vd1 = sVb + (vrow * 40 + 16 + vcb) * 2;
            uint32_t vh[8];
            LDSM4T(vh[0], vh[1], vh[2], vh[3], vd0);
            LDSM4T(vh[4], vh[5], vh[6], vh[7], vd1);
            mma16816h(O[0], pa, vh[0], vh[1]);
            mma16816h(O[1], pa, vh[2], vh[3]);
            mma16816h(O[2], pa, vh[4], vh[5]);
            mma16816h(O[3], pa, vh[6], vh[7]);
        }
    }

    // ---- output: normalize, store fp16 single for proj GEMM ----
    float li0 = 1.f / lrow0, li1 = 1.f / lrow1;
#pragma unroll
    for (int jd = 0; jd < 4; jd++) {
        int d = jd * 8 + qc2;
        if (row0 < NTOK) {
            size_t idx = ((size_t)(b * NTOK + row0)) * CDIM + h * HD + d;
            *(uint32_t*)(g_A16 + idx) = pack_h2(O[jd][0] * li0, O[jd][1] * li0);
        }
        if (row0 + 8 < NTOK) {
            size_t idx = ((size_t)(b * NTOK + row0 + 8)) * CDIM + h * HD + d;
            *(uint32_t*)(g_A16 + idx) = pack_h2(O[jd][2] * li1, O[jd][3] * li1);
        }
    }
}

// =====================================================================
extern "C" void kernel_launch(void* const* d_in, const int* in_sizes, int n_in,
                              void* d_out, int out_size)
{
    const float* x    = (const float*)d_in[0];
    const float* Wqkv = (const float*)d_in[1];
    const float* bqkv = (const float*)d_in[2];
    const float* Wprj = (const float*)d_in[3];
    const float* bprj = (const float*)d_in[4];
    const float* btt  = (const float*)d_in[5];
    const float* btm  = (const float*)d_in[6];
    const float* ttt  = (const float*)d_in[7];
    const float* tgt  = (const float*)d_in[8];
    const float* ttl  = (const float*)d_in[9];
    const float* tgl  = (const float*)d_in[10];
    float* out = (float*)d_out;

    cudaFuncSetAttribute(attn_mma_kernel, cudaFuncAttributeMaxDynamicSharedMemorySize,
                         ATT_SMEM_BYTES);

    __nv_bfloat16 *pAhi, *pAlo, *pWhi, *pWlo;
    __half *pPhi, *pPlo, *pA16;
    cudaGetSymbolAddress((void**)&pAhi, g_Ahi);
    cudaGetSymbolAddress((void**)&pAlo, g_Alo);
    cudaGetSymbolAddress((void**)&pA16, g_A16);
    cudaGetSymbolAddress((void**)&pWhi, g_Whi);
    cudaGetSymbolAddress((void**)&pWlo, g_Wlo);
    cudaGetSymbolAddress((void**)&pPhi, g_Phi);
    cudaGetSymbolAddress((void**)&pPlo, g_Plo);

    const int n4 = MROWS * CDIM / 4;

    build_bias_kernel<<<dim3((NTOK * NTOK + 255) / 256, NH), 256>>>(
        btt, btm, ttt, tgt, ttl, tgl);
    split_kernel<<<(n4 + 255) / 256, 256>>>(x, pAhi, pAlo, n4);
    tsplit_kernel<<<dim3(1536 / 32, 512 / 32), dim3(32, 8)>>>(Wqkv, pWhi, pWlo, 512, 1536);
    tsplit_h_kernel<<<dim3(512 / 32, 512 / 32), dim3(32, 8)>>>(Wprj, pPhi, pPlo, 512, 512);
    gemm_qkv_kernel<<<dim3(12, 93), 256>>>(pAhi, pAlo, pWhi, pWlo, bqkv);
    attn_mma_kernel<<<dim3(6, NH, NB), 256, ATT_SMEM_BYTES>>>();
    gemm_proj_kernel<<<dim3(4, 93), 256>>>(pA16, pPhi, pPlo, bprj, out);
}

// round 17
// speedup vs baseline: 2.6006x; 1.2335x over previous
#include <cuda_runtime.h>
#include <cuda_bf16.h>
#include <cuda_fp16.h>
#include <cstdint>
#include <math.h>

#define NB 16
#define NH 16
#define NTOK 740
#define HD 32
#define CDIM 512
#define MROWS (NB * NTOK)            // 11840
#define BHND (NB * NH * NTOK * HD)   // 6062080
#define QK_SCALE 0.17677669529663687f

// ---------------- device scratch (all-fp16 pipeline) ----------------
__device__ __align__(16) __nv_bfloat16 g_biasb[NH * NTOK * NTOK + 256];
__device__ __align__(16) __half g_x16[MROWS * CDIM];        // x fp16 (qkv A side)
__device__ __align__(16) __half g_A16[MROWS * CDIM];        // attn out (proj A side)
__device__ __align__(16) __half g_Wqh[3 * CDIM * CDIM];     // W_qkv^T fp16 hi
__device__ __align__(16) __half g_Wql[3 * CDIM * CDIM];     // W_qkv^T fp16 lo
__device__ __align__(16) __half g_Phi[CDIM * CDIM];         // W_proj^T fp16 hi
__device__ __align__(16) __half g_Plo[CDIM * CDIM];         // W_proj^T fp16 lo
__device__ __align__(16) __half g_q16[BHND];                // q single fp16 (scaled)
__device__ __align__(16) __half g_k16h[BHND];               // k fp16 hi
__device__ __align__(16) __half g_k16l[BHND];               // k fp16 lo
__device__ __align__(16) __half g_v16[BHND];                // v single fp16

// ================= helpers (base-ISA only: mma.sync / ldmatrix) =================
__device__ __forceinline__ uint32_t smem_u32(const void* p) {
    uint32_t a;
    asm("{ .reg .u64 t; cvta.to.shared.u64 t, %1; cvt.u32.u64 %0, t; }" : "=r"(a) : "l"(p));
    return a;
}

__device__ __forceinline__ void mma16816h(float c[4], const uint32_t a[4],
                                          uint32_t b0, uint32_t b1) {
    asm volatile(
        "mma.sync.aligned.m16n8k16.row.col.f32.f16.f16.f32 "
        "{%0,%1,%2,%3}, {%4,%5,%6,%7}, {%8,%9}, {%0,%1,%2,%3};"
        : "+f"(c[0]), "+f"(c[1]), "+f"(c[2]), "+f"(c[3])
        : "r"(a[0]), "r"(a[1]), "r"(a[2]), "r"(a[3]), "r"(b0), "r"(b1));
}

#define LDSM4(R0, R1, R2, R3, ADDR) \
    asm volatile("ldmatrix.sync.aligned.m8n8.x4.shared.b16 {%0,%1,%2,%3}, [%4];" \
        : "=r"(R0), "=r"(R1), "=r"(R2), "=r"(R3) : "r"(ADDR))

#define LDSM4T(R0, R1, R2, R3, ADDR) \
    asm volatile("ldmatrix.sync.aligned.m8n8.x4.trans.shared.b16 {%0,%1,%2,%3}, [%4];" \
        : "=r"(R0), "=r"(R1), "=r"(R2), "=r"(R3) : "r"(ADDR))

// split fp32 pair -> packed fp16 hi pair + lo (residual) pair
__device__ __forceinline__ void split_pack2h(float f0, float f1,
                                             uint32_t& hi, uint32_t& lo) {
    __half h0 = __float2half_rn(f0);
    __half h1 = __float2half_rn(f1);
    __half2 hv = __halves2half2(h0, h1);
    hi = *reinterpret_cast<uint32_t*>(&hv);
    __half2 lv = __halves2half2(__float2half_rn(f0 - __half2float(h0)),
                                __float2half_rn(f1 - __half2float(h1)));
    lo = *reinterpret_cast<uint32_t*>(&lv);
}

__device__ __forceinline__ uint32_t pack_h2(float f0, float f1) {
    __half2 h = __floats2half2_rn(f0, f1);
    return *reinterpret_cast<uint32_t*>(&h);
}

__device__ __forceinline__ int imin(int a, int b) { return a < b ? a : b; }

// =====================================================================
// Bias assembly (bf16 output)
// =====================================================================
__global__ void build_bias_kernel(const float* __restrict__ btt,
                                  const float* __restrict__ btm,
                                  const float* __restrict__ ttt,
                                  const float* __restrict__ tgt,
                                  const float* __restrict__ ttl,
                                  const float* __restrict__ tgl)
{
    int p = blockIdx.x * 256 + threadIdx.x;
    if (p >= NTOK * NTOK) return;
    int h = blockIdx.y;
    int i = p / NTOK, j = p - i * NTOK;
    float v;
    if (i < 256) {
        if (j < 256) {
            int ai = i >> 4, bi = i & 15, aj = j >> 4, bj = j & 15;
            int idx = (ai - aj + 15) * 31 + (bi - bj + 15);
            v = btm[idx * NH + h];
        } else {
            v = tgt[h * 256 + i] + tgl[h * 484 + (j - 256)];
        }
    } else {
        int i2 = i - 256;
        if (j < 256) {
            v = ttt[h * 484 + i2] + ttl[h * 256 + j];
        } else {
            int j2 = j - 256;
            int ai = i2 / 22, bi = i2 - ai * 22;
            int aj = j2 / 22, bj = j2 - aj * 22;
            int idx = (ai - aj + 21) * 43 + (bi - bj + 21);
            v = btt[idx * NH + h];
        }
    }
    g_biasb[h * NTOK * NTOK + p] = __float2bfloat16(v);
}

// =====================================================================
// fp32 -> fp16 convert, elementwise
// =====================================================================
__global__ void conv16_kernel(const float* __restrict__ in,
                              __half* __restrict__ o16, int n4)
{
    int i = blockIdx.x * 256 + threadIdx.x;
    if (i >= n4) return;
    float4 v = ((const float4*)in)[i];
    uint2 r;
    r.x = pack_h2(v.x, v.y);
    r.y = pack_h2(v.z, v.w);
    ((uint2*)o16)[i] = r;
}

// =====================================================================
// Transpose + split: W[K,NN] fp32 -> hi/lo[NN,K] fp16
// =====================================================================
__global__ void tsplit_h_kernel(const float* __restrict__ W,
                                __half* __restrict__ hi,
                                __half* __restrict__ lo, int K, int NN)
{
    __shared__ float t[32][33];
    int nb = blockIdx.x * 32, kb = blockIdx.y * 32;
    int tx = threadIdx.x, ty = threadIdx.y;
#pragma unroll
    for (int i = 0; i < 32; i += 8)
        t[ty + i][tx] = W[(size_t)(kb + ty + i) * NN + nb + tx];
    __syncthreads();
#pragma unroll
    for (int i = 0; i < 32; i += 8) {
        float v = t[tx][ty + i];
        __half h = __float2half_rn(v);
        __half l = __float2half_rn(v - __half2float(h));
        size_t o = (size_t)(nb + ty + i) * K + kb + tx;
        hi[o] = h;
        lo[o] = l;
    }
}

// =====================================================================
// HMMA fp16 GEMM: C[128m x 128n] = A16[.,512] @ (Bhi+Blo)[.,512]^T (+bias)
// A single fp16, B fp16 2-term. 2 MMAs per accumulated product.
// MODE 0: qkv epilogue -> q fp16 scaled, k fp16 hi/lo, v fp16
// MODE 1: proj epilogue -> fp32 out
// =====================================================================
template <int MODE>
__global__ void __launch_bounds__(256, 2) gemm_f16_kernel(
    const __half* __restrict__ A16,
    const __half* __restrict__ Bhi, const __half* __restrict__ Blo,
    const float* __restrict__ bias, float* __restrict__ out)
{
    __shared__ __align__(16) __half sA[128 * 40];
    __shared__ __align__(16) __half sB[2][128 * 40];
    int tid = threadIdx.x, lane = tid & 31, wid = tid >> 5;
    int wm = wid >> 1, wn = wid & 1;
    int m0 = blockIdx.y * 128, n0 = blockIdx.x * 128;
    int qr = lane >> 2, qc2 = (lane & 3) * 2;

    float acc[16][4];
#pragma unroll
    for (int i = 0; i < 16; i++)
#pragma unroll
        for (int j = 0; j < 4; j++) acc[i][j] = 0.f;

    int r = tid >> 1, cb = (tid & 1) * 16;
    int arow = imin(m0 + r, MROWS - 1);
    int brow = n0 + r;
    const uint4* gA0 = (const uint4*)(A16 + (size_t)arow * CDIM);
    const uint4* gB0 = (const uint4*)(Bhi + (size_t)brow * CDIM);
    const uint4* gB1 = (const uint4*)(Blo + (size_t)brow * CDIM);
    uint32_t sAb = smem_u32(sA);
    uint32_t sBb = smem_u32(sB);

    for (int k0 = 0; k0 < CDIM; k0 += 32) {
        int kq = (k0 + cb) >> 3;
        uint4 va0 = gA0[kq], va0b = gA0[kq + 1];
        uint4 vb0 = gB0[kq], vb0b = gB0[kq + 1];
        uint4 vb1 = gB1[kq], vb1b = gB1[kq + 1];
        if (k0) __syncthreads();
        *(uint4*)(&sA[r * 40 + cb]) = va0;
        *(uint4*)(&sA[r * 40 + cb + 8]) = va0b;
        *(uint4*)(&sB[0][r * 40 + cb]) = vb0;
        *(uint4*)(&sB[0][r * 40 + cb + 8]) = vb0b;
        *(uint4*)(&sB[1][r * 40 + cb]) = vb1;
        *(uint4*)(&sB[1][r * 40 + cb + 8]) = vb1b;
        __syncthreads();

#pragma unroll
        for (int kc = 0; kc < 2; kc++) {
            uint32_t a16[2][4];
#pragma unroll
            for (int mb = 0; mb < 2; mb++) {
                uint32_t ad = sAb +
                    ((wm * 32 + mb * 16 + (lane & 15)) * 40 + kc * 16 + (lane >> 4) * 8) * 2;
                LDSM4(a16[mb][0], a16[mb][1], a16[mb][2], a16[mb][3], ad);
            }
#pragma unroll
            for (int jp = 0; jp < 4; jp++) {
                uint32_t bd = sBb +
                    ((wn * 64 + jp * 16 + (lane & 7) + ((lane >> 3) & 1) * 8) * 40 +
                     kc * 16 + (lane >> 4) * 8) * 2;
                uint32_t bh[4], bl[4];
                LDSM4(bh[0], bh[1], bh[2], bh[3], bd);
                LDSM4(bl[0], bl[1], bl[2], bl[3], bd + 10240);
#pragma unroll
                for (int mb = 0; mb < 2; mb++) {
                    float* c0 = acc[mb * 8 + jp * 2];
                    float* c1 = acc[mb * 8 + jp * 2 + 1];
                    mma16816h(c0, a16[mb], bh[0], bh[2]);
                    mma16816h(c0, a16[mb], bl[0], bl[2]);
                    mma16816h(c1, a16[mb], bh[1], bh[3]);
                    mma16816h(c1, a16[mb], bl[1], bl[3]);
                }
            }
        }
    }

    // ---------------- epilogue ----------------
#pragma unroll
    for (int mb = 0; mb < 2; mb++) {
        int gm0 = m0 + wm * 32 + mb * 16 + qr;
#pragma unroll
        for (int half = 0; half < 2; half++) {
            int gm = gm0 + half * 8;
            if (gm >= MROWS) continue;
            int bb = gm / NTOK;
            int nn = gm - bb * NTOK;
#pragma unroll
            for (int j = 0; j < 8; j++) {
                int col = n0 + wn * 64 + j * 8 + qc2;
                float v0 = acc[mb * 8 + j][half * 2 + 0];
                float v1 = acc[mb * 8 + j][half * 2 + 1];
                float2 bv = *(const float2*)(bias + col);
                v0 += bv.x;
                v1 += bv.y;
                if (MODE == 0) {
                    int s = col >> 9, hh = (col >> 5) & 15, d = col & 31;
                    size_t idx = ((size_t)((bb * NH + hh) * NTOK + nn)) * HD + d;
                    if (s == 0) {
                        *(uint32_t*)(g_q16 + idx) =
                            pack_h2(v0 * QK_SCALE, v1 * QK_SCALE);
                    } else if (s == 1) {
                        uint32_t hi, lo;
                        split_pack2h(v0, v1, hi, lo);
                        *(uint32_t*)(g_k16h + idx) = hi;
                        *(uint32_t*)(g_k16l + idx) = lo;
                    } else {
                        *(uint32_t*)(g_v16 + idx) = pack_h2(v0, v1);
                    }
                } else {
                    float2 o = make_float2(v0, v1);
                    *(float2*)(out + (size_t)gm * CDIM + col) = o;
                }
            }
        }
    }
}

// =====================================================================
// HMMA flash attention, all-fp16: q-tile 128 x key-tile 128, hd=32
// QK: q single fp16 x k fp16 2-term (2 MMAs); PV: P fp16 x V fp16 (1 MMA)
// smem: Q 10240B | K(hi,lo) 20480B | V 10240B = 40960B
// =====================================================================
#define ATT_SMEM_BYTES 40960

__global__ void __launch_bounds__(256, 2) attn_mma_kernel()
{
    extern __shared__ __align__(16) char smc[];
    __half* sQ = (__half*)smc;                 // single, 5120 elems
    __half* sK = (__half*)smc + 5120;          // hi +0, lo +5120 elems
    __half* sV = (__half*)smc + 15360;         // single, 5120 elems
    uint32_t sQb = smem_u32(sQ);
    uint32_t sKb = smem_u32(sK);
    uint32_t sVb = smem_u32(sV);

    int b = blockIdx.z, h = blockIdx.y, q0 = blockIdx.x * 128;
    int tid = threadIdx.x, lane = tid & 31, wid = tid >> 5;
    int qr = lane >> 2, qc2 = (lane & 3) * 2;
    size_t ho = (size_t)((b * NH + h) * NTOK) * HD;

    // load Q tile (single fp16), rows clamped
    {
        int r = tid >> 1, cb = (tid & 1) * 16, ci = cb >> 3;
        int gr = imin(q0 + r, NTOK - 1);
        const uint4* s0 = (const uint4*)(g_q16 + ho + (size_t)gr * HD);
        *(uint4*)(sQ + r * 40 + cb) = s0[ci];
        *(uint4*)(sQ + r * 40 + cb + 8) = s0[ci + 1];
    }
    __syncthreads();

    // Q fragments, kept in registers for all 6 key tiles
    uint32_t qf[2][4];
#pragma unroll
    for (int kc = 0; kc < 2; kc++) {
        uint32_t ad = sQb + ((wid * 16 + (lane & 15)) * 40 + kc * 16 + (lane >> 4) * 8) * 2;
        LDSM4(qf[kc][0], qf[kc][1], qf[kc][2], qf[kc][3], ad);
    }

    float O[4][4];
#pragma unroll
    for (int i = 0; i < 4; i++)
#pragma unroll
        for (int j = 0; j < 4; j++) O[i][j] = 0.f;
    float mrow0 = -1e30f, mrow1 = -1e30f, lrow0 = 0.f, lrow1 = 0.f;

    int row0 = q0 + wid * 16 + qr;           // global q row (within batch-head)
    const __nv_bfloat16* bias0 =
        g_biasb + ((size_t)h * NTOK + imin(row0, NTOK - 1)) * NTOK;
    const __nv_bfloat16* bias1 =
        g_biasb + ((size_t)h * NTOK + imin(row0 + 8, NTOK - 1)) * NTOK;

    for (int kt = 0; kt < 6; kt++) {
        int k0 = kt * 128;
        if (kt) __syncthreads();
        // load K (fp16 hi/lo), V (fp16 single)
        {
            int r = tid >> 1, cb = (tid & 1) * 16, ci = cb >> 3;
            int gr = imin(k0 + r, NTOK - 1);
            const uint4* kh = (const uint4*)(g_k16h + ho + (size_t)gr * HD);
            const uint4* kl = (const uint4*)(g_k16l + ho + (size_t)gr * HD);
            const uint4* vh = (const uint4*)(g_v16 + ho + (size_t)gr * HD);
            *(uint4*)(sK + r * 40 + cb) = kh[ci];
            *(uint4*)(sK + r * 40 + cb + 8) = kh[ci + 1];
            *(uint4*)(sK + 5120 + r * 40 + cb) = kl[ci];
            *(uint4*)(sK + 5120 + r * 40 + cb + 8) = kl[ci + 1];
            *(uint4*)(sV + r * 40 + cb) = vh[ci];
            *(uint4*)(sV + r * 40 + cb + 8) = vh[ci + 1];
        }
        __syncthreads();

        // ---- S = Q K^T (q single fp16, k 2-term fp16) ----
        float S[16][4];
#pragma unroll
        for (int i = 0; i < 16; i++)
#pragma unroll
            for (int j = 0; j < 4; j++) S[i][j] = 0.f;

#pragma unroll
        for (int kc = 0; kc < 2; kc++) {
#pragma unroll
            for (int jp = 0; jp < 8; jp++) {
                uint32_t bd = sKb +
                    ((jp * 16 + (lane & 7) + ((lane >> 3) & 1) * 8) * 40 +
                     kc * 16 + (lane >> 4) * 8) * 2;
                uint32_t bh[4], bl[4];
                LDSM4(bh[0], bh[1], bh[2], bh[3], bd);
                LDSM4(bl[0], bl[1], bl[2], bl[3], bd + 10240);
                float* c0 = S[jp * 2];
                float* c1 = S[jp * 2 + 1];
                mma16816h(c0, qf[kc], bh[0], bh[2]);
                mma16816h(c0, qf[kc], bl[0], bl[2]);
                mma16816h(c1, qf[kc], bh[1], bh[3]);
                mma16816h(c1, qf[kc], bl[1], bl[3]);
            }
        }

        // ---- bias (bf16) + key mask ----
        int kv = NTOK - k0;
#pragma unroll
        for (int j = 0; j < 16; j++) {
            int c = j * 8 + qc2;
            float2 b0 = __bfloat1622float2(
                *(const __nv_bfloat162*)(bias0 + k0 + c));
            float2 b1 = __bfloat1622float2(
                *(const __nv_bfloat162*)(bias1 + k0 + c));
            S[j][0] += b0.x; S[j][1] += b0.y;
            S[j][2] += b1.x; S[j][3] += b1.y;
            if (c >= kv)     { S[j][0] = -1e30f; S[j][2] = -1e30f; }
            if (c + 1 >= kv) { S[j][1] = -1e30f; S[j][3] = -1e30f; }
        }

        // ---- online softmax ----
        float m0l = -1e30f, m1l = -1e30f;
#pragma unroll
        for (int j = 0; j < 16; j++) {
            m0l = fmaxf(m0l, fmaxf(S[j][0], S[j][1]));
            m1l = fmaxf(m1l, fmaxf(S[j][2], S[j][3]));
        }
        m0l = fmaxf(m0l, __shfl_xor_sync(0xffffffffu, m0l, 1));
        m0l = fmaxf(m0l, __shfl_xor_sync(0xffffffffu, m0l, 2));
        m1l = fmaxf(m1l, __shfl_xor_sync(0xffffffffu, m1l, 1));
        m1l = fmaxf(m1l, __shfl_xor_sync(0xffffffffu, m1l, 2));
        float mn0 = fmaxf(mrow0, m0l), mn1 = fmaxf(mrow1, m1l);
        float corr0 = __expf(mrow0 - mn0), corr1 = __expf(mrow1 - mn1);
        mrow0 = mn0; mrow1 = mn1;
        float s0 = 0.f, s1 = 0.f;
#pragma unroll
        for (int j = 0; j < 16; j++) {
            S[j][0] = __expf(S[j][0] - mn0); s0 += S[j][0];
            S[j][1] = __expf(S[j][1] - mn0); s0 += S[j][1];
            S[j][2] = __expf(S[j][2] - mn1); s1 += S[j][2];
            S[j][3] = __expf(S[j][3] - mn1); s1 += S[j][3];
        }
        s0 += __shfl_xor_sync(0xffffffffu, s0, 1);
        s0 += __shfl_xor_sync(0xffffffffu, s0, 2);
        s1 += __shfl_xor_sync(0xffffffffu, s1, 1);
        s1 += __shfl_xor_sync(0xffffffffu, s1, 2);
        lrow0 = lrow0 * corr0 + s0;
        lrow1 = lrow1 * corr1 + s1;
#pragma unroll
        for (int jd = 0; jd < 4; jd++) {
            O[jd][0] *= corr0; O[jd][1] *= corr0;
            O[jd][2] *= corr1; O[jd][3] *= corr1;
        }

        // ---- O += P V : P fp16, V single fp16 ----
#pragma unroll
        for (int kc = 0; kc < 8; kc++) {
            uint32_t pa[4];
            pa[0] = pack_h2(S[2 * kc][0], S[2 * kc][1]);
            pa[1] = pack_h2(S[2 * kc][2], S[2 * kc][3]);
            pa[2] = pack_h2(S[2 * kc + 1][0], S[2 * kc + 1][1]);
            pa[3] = pack_h2(S[2 * kc + 1][2], S[2 * kc + 1][3]);
            uint32_t vrow = kc * 16 + (lane & 7) + ((lane >> 3) & 1) * 8;
            uint32_t vcb = (lane >> 4) * 8;
            uint32_t vd0 = sVb + (vrow * 40 + vcb) * 2;
            uint32_t vd1 = sVb + (vrow * 40 + 16 + vcb) * 2;
            uint32_t vh[8];
            LDSM4T(vh[0], vh[1], vh[2], vh[3], vd0);
            LDSM4T(vh[4], vh[5], vh[6], vh[7], vd1);
            mma16816h(O[0], pa, vh[0], vh[1]);
            mma16816h(O[1], pa, vh[2], vh[3]);
            mma16816h(O[2], pa, vh[4], vh[5]);
            mma16816h(O[3], pa, vh[6], vh[7]);
        }
    }

    // ---- output: normalize, store fp16 single for proj GEMM ----
    float li0 = 1.f / lrow0, li1 = 1.f / lrow1;
#pragma unroll
    for (int jd = 0; jd < 4; jd++) {
        int d = jd * 8 + qc2;
        if (row0 < NTOK) {
            size_t idx = ((size_t)(b * NTOK + row0)) * CDIM + h * HD + d;
            *(uint32_t*)(g_A16 + idx) = pack_h2(O[jd][0] * li0, O[jd][1] * li0);
        }
        if (row0 + 8 < NTOK) {
            size_t idx = ((size_t)(b * NTOK + row0 + 8)) * CDIM + h * HD + d;
            *(uint32_t*)(g_A16 + idx) = pack_h2(O[jd][2] * li1, O[jd][3] * li1);
        }
    }
}

// =====================================================================
extern "C" void kernel_launch(void* const* d_in, const int* in_sizes, int n_in,
                              void* d_out, int out_size)
{
    const float* x    = (const float*)d_in[0];
    const float* Wqkv = (const float*)d_in[1];
    const float* bqkv = (const float*)d_in[2];
    const float* Wprj = (const float*)d_in[3];
    const float* bprj = (const float*)d_in[4];
    const float* btt  = (const float*)d_in[5];
    const float* btm  = (const float*)d_in[6];
    const float* ttt  = (const float*)d_in[7];
    const float* tgt  = (const float*)d_in[8];
    const float* ttl  = (const float*)d_in[9];
    const float* tgl  = (const float*)d_in[10];
    float* out = (float*)d_out;

    cudaFuncSetAttribute(attn_mma_kernel, cudaFuncAttributeMaxDynamicSharedMemorySize,
                         ATT_SMEM_BYTES);

    __half *pX16, *pA16, *pWqh, *pWql, *pPhi, *pPlo;
    cudaGetSymbolAddress((void**)&pX16, g_x16);
    cudaGetSymbolAddress((void**)&pA16, g_A16);
    cudaGetSymbolAddress((void**)&pWqh, g_Wqh);
    cudaGetSymbolAddress((void**)&pWql, g_Wql);
    cudaGetSymbolAddress((void**)&pPhi, g_Phi);
    cudaGetSymbolAddress((void**)&pPlo, g_Plo);

    const int n4 = MROWS * CDIM / 4;

    build_bias_kernel<<<dim3((NTOK * NTOK + 255) / 256, NH), 256>>>(
        btt, btm, ttt, tgt, ttl, tgl);
    conv16_kernel<<<(n4 + 255) / 256, 256>>>(x, pX16, n4);
    tsplit_h_kernel<<<dim3(1536 / 32, 512 / 32), dim3(32, 8)>>>(Wqkv, pWqh, pWql, 512, 1536);
    tsplit_h_kernel<<<dim3(512 / 32, 512 / 32), dim3(32, 8)>>>(Wprj, pPhi, pPlo, 512, 512);
    gemm_f16_kernel<0><<<dim3(12, 93), 256>>>(pX16, pWqh, pWql, bqkv, nullptr);
    attn_mma_kernel<<<dim3(6, NH, NB), 256, ATT_SMEM_BYTES>>>();
    gemm_f16_kernel<1><<<dim3(4, 93), 256>>>(pA16, pPhi, pPlo, bprj, out);
}